// round 8
// baseline (speedup 1.0000x reference)
#include <cuda_runtime.h>
#include <cuda_bf16.h>
#include <cstdint>

#define DD 128
#define MAXN 100000
#define MAXE 655360
#define LDC 72                       // smem chunk stride (bf16), conflict-free ldmatrix

// ---- scratch (no allocs allowed) -------------------------------------------
__device__ __align__(16) float g_A[(size_t)MAXN * DD];   // (1+eps)x + aggr
__device__ __align__(16) float g_Y[(size_t)MAXN * DD];   // layer outputs (in-place L2)
// [0:128) sum1 [128:256) sq1 [256:384) sum2 [384:512) sq2
// [512:640) s1 [640:768) t1 [768:896) s2 [896:1024) t2
__device__ float g_stat[8 * DD];
__device__ int   g_i64flag;
__device__ __align__(16) __nv_bfloat16 g_Whi[2][DD * DD];
__device__ __align__(16) __nv_bfloat16 g_Wlo[2][DD * DD];
// CSR scratch
__device__ int g_cnt[MAXN + 1];
__device__ int g_off[MAXN + 1];
__device__ int g_cur[MAXN];
__device__ int g_srcid[MAXE];
__device__ int g_blksum[256];
__device__ int g_blkoff[256];

#define SMEMU32(p) ((uint32_t)__cvta_generic_to_shared(p))

__device__ __forceinline__ void ldx4(uint32_t* r, uint32_t addr) {
    asm volatile("ldmatrix.sync.aligned.m8n8.x4.shared.b16 {%0,%1,%2,%3}, [%4];"
                 : "=r"(r[0]), "=r"(r[1]), "=r"(r[2]), "=r"(r[3]) : "r"(addr));
}
__device__ __forceinline__ void mma16816(float* c, const uint32_t* a, uint32_t b0, uint32_t b1) {
    asm volatile("mma.sync.aligned.m16n8k16.row.col.f32.bf16.bf16.f32 "
                 "{%0,%1,%2,%3}, {%4,%5,%6,%7}, {%8,%9}, {%0,%1,%2,%3};"
                 : "+f"(c[0]), "+f"(c[1]), "+f"(c[2]), "+f"(c[3])
                 : "r"(a[0]), "r"(a[1]), "r"(a[2]), "r"(a[3]), "r"(b0), "r"(b1));
}

// ---------------------------------------------------------------------------
__global__ void k_detect(const int* __restrict__ w, int E) {
    __shared__ int s_or;
    if (threadIdx.x == 0) s_or = 0;
    __syncthreads();
    int total = 2 * E;
    int step = total / 4096; if (step < 2) step = 2;
    int acc = 0;
    for (int i = threadIdx.x; i < 4096; i += blockDim.x) {
        long long idx = ((long long)i * step) | 1;
        if (idx < total) acc |= w[idx];
    }
    atomicOr(&s_or, acc);
    __syncthreads();
    if (threadIdx.x == 0) g_i64flag = (s_or == 0) ? 1 : 0;
}

// ---------------------------------------------------------------------------
__global__ void k_zero(int Nn) {
    if (blockIdx.x == 0 && threadIdx.x < 256) {
        g_stat[threadIdx.x] = 0.0f;
        g_stat[threadIdx.x + 256] = 0.0f;
    }
    for (int i = blockIdx.x * blockDim.x + threadIdx.x; i < Nn; i += gridDim.x * blockDim.x)
        g_cnt[i] = 0;
}

// ---------------------------------------------------------------------------
__global__ void k_hist(const int* __restrict__ w, int E) {
    int e = blockIdx.x * blockDim.x + threadIdx.x;
    if (e >= E) return;
    int d = g_i64flag ? __ldg(&w[2 * (E + e)]) : __ldg(&w[E + e]);
    atomicAdd(&g_cnt[d], 1);
}

// ---- 3-stage exclusive scan of g_cnt -> g_off (chunk = 512 per block) ------
__global__ void k_scanA(int Nn) {
    __shared__ int sm[256];
    int b = blockIdx.x, t = threadIdx.x;
    int base = b * 512;
    int v = 0;
    if (base + t < Nn)       v += g_cnt[base + t];
    if (base + t + 256 < Nn) v += g_cnt[base + t + 256];
    sm[t] = v; __syncthreads();
    for (int o = 128; o > 0; o >>= 1) { if (t < o) sm[t] += sm[t + o]; __syncthreads(); }
    if (t == 0) g_blksum[b] = sm[0];
}
__global__ void k_scanB(int nblk) {
    __shared__ int sm[256];
    int t = threadIdx.x;
    int v = (t < nblk) ? g_blksum[t] : 0;
    sm[t] = v; __syncthreads();
    for (int o = 1; o < 256; o <<= 1) {
        int a = (t >= o) ? sm[t - o] : 0;
        __syncthreads(); sm[t] += a; __syncthreads();
    }
    if (t < nblk) g_blkoff[t] = sm[t] - v;   // exclusive
}
__global__ void k_scanC(int Nn) {
    __shared__ int sm[256];
    int b = blockIdx.x, t = threadIdx.x;
    int i0 = b * 512 + 2 * t, i1 = i0 + 1;
    int c0 = (i0 < Nn) ? g_cnt[i0] : 0;
    int c1 = (i1 < Nn) ? g_cnt[i1] : 0;
    int v = c0 + c1;
    sm[t] = v; __syncthreads();
    for (int o = 1; o < 256; o <<= 1) {
        int a = (t >= o) ? sm[t - o] : 0;
        __syncthreads(); sm[t] += a; __syncthreads();
    }
    int excl = sm[t] - v + g_blkoff[b];
    if (i0 < Nn) { g_off[i0] = excl;      g_cur[i0] = excl; }
    if (i1 < Nn) { g_off[i1] = excl + c0; g_cur[i1] = excl + c0; }
}

// ---------------------------------------------------------------------------
__global__ void k_fill(const int* __restrict__ w, int E) {
    int e = blockIdx.x * blockDim.x + threadIdx.x;
    if (e >= E) return;
    int s, d;
    if (g_i64flag) { s = __ldg(&w[2 * e]); d = __ldg(&w[2 * (E + e)]); }
    else           { s = __ldg(&w[e]);     d = __ldg(&w[E + e]); }
    int p = atomicAdd(&g_cur[d], 1);
    g_srcid[p] = s;
}

// ---------------------------------------------------------------------------
// One warp per node: A[d] = (1+eps)*x[d] + sum_{e in bucket(d)} x[src(e)]
__global__ __launch_bounds__(256) void k_aggr(const float4* __restrict__ x,
                                              const float* __restrict__ eps, int Nn, int E) {
    int gw = (blockIdx.x * blockDim.x + threadIdx.x) >> 5;
    int lane = threadIdx.x & 31;
    if (gw >= Nn) return;
    float e = 1.0f + __ldg(eps);
    int beg = g_off[gw];
    int end = (gw + 1 < Nn) ? g_off[gw + 1] : E;
    float4 a = __ldg(&x[(size_t)gw * 32 + lane]);
    float4 acc = make_float4(a.x * e, a.y * e, a.z * e, a.w * e);
    int i = beg;
    for (; i + 3 < end; i += 4) {
        int s0 = __ldg(&g_srcid[i + 0]), s1 = __ldg(&g_srcid[i + 1]);
        int s2 = __ldg(&g_srcid[i + 2]), s3 = __ldg(&g_srcid[i + 3]);
        float4 v0 = __ldg(&x[(size_t)s0 * 32 + lane]);
        float4 v1 = __ldg(&x[(size_t)s1 * 32 + lane]);
        float4 v2 = __ldg(&x[(size_t)s2 * 32 + lane]);
        float4 v3 = __ldg(&x[(size_t)s3 * 32 + lane]);
        acc.x += v0.x + v1.x + v2.x + v3.x;
        acc.y += v0.y + v1.y + v2.y + v3.y;
        acc.z += v0.z + v1.z + v2.z + v3.z;
        acc.w += v0.w + v1.w + v2.w + v3.w;
    }
    for (; i < end; i++) {
        int s = __ldg(&g_srcid[i]);
        float4 v = __ldg(&x[(size_t)s * 32 + lane]);
        acc.x += v.x; acc.y += v.y; acc.z += v.z; acc.w += v.w;
    }
    *reinterpret_cast<float4*>(&g_A[(size_t)gw * DD + lane * 4]) = acc;
}

// ---------------------------------------------------------------------------
__global__ void k_prep(const float* __restrict__ W1, const float* __restrict__ W2) {
    int i = blockIdx.x * blockDim.x + threadIdx.x;
    if (i >= 2 * DD * DD) return;
    int layer = i >> 14, j = i & (DD * DD - 1);
    float v = (layer == 0) ? W1[j] : W2[j];
    __nv_bfloat16 h = __float2bfloat16_rn(v);
    g_Whi[layer][j] = h;
    g_Wlo[layer][j] = __float2bfloat16_rn(v - __bfloat162float(h));
}

// ---------------------------------------------------------------------------
// mma.sync GEMM: CTA = 128x128 tile, K in 2 chunks of 64 (73.7KB smem -> 2 CTAs/SM).
// bf16 hi/lo x3 emulation; fused epilogue: bias + store + BN sum/sumsq.
// dynsm: A_hi @0, A_lo @18432, W_hi @36864, W_lo @55296 (128 x LDC bf16 each)
template <int LAYER>
__global__ __launch_bounds__(256, 2) void k_gemm_tc(const float* __restrict__ bias, int Nn) {
    extern __shared__ char dynsm[];
    __shared__ float s_bias[DD];
    __shared__ float s_s[DD], s_t[DD];
    __shared__ float s_sum[DD], s_sq[DD];

    const uint32_t sbase = SMEMU32(dynsm);
    const uint32_t AHI = sbase, ALO = sbase + 18432, WHI = sbase + 36864, WLO = sbase + 55296;

    int tid = threadIdx.x, wid = tid >> 5, lane = tid & 31;
    if (tid < DD) {
        s_bias[tid] = __ldg(&bias[tid]);
        s_sum[tid] = 0.f; s_sq[tid] = 0.f;
        if (LAYER == 2) { s_s[tid] = g_stat[4 * DD + tid]; s_t[tid] = g_stat[5 * DD + tid]; }
    }
    __syncthreads();

    int row0 = blockIdx.x * 128;
    int warp_m = wid & 3, warp_n = wid >> 2;          // 4 x 2 warp grid
    int aRow = warp_m * 32 + (lane & 15);
    int aKh  = (lane >> 4) * 8;
    int bRow = warp_n * 64 + (lane & 7) + ((lane >> 4) & 1) * 8;
    int bKh  = ((lane >> 3) & 1) * 8;

    float acc[2][8][4];
#pragma unroll
    for (int mt = 0; mt < 2; mt++)
#pragma unroll
        for (int nt = 0; nt < 8; nt++)
#pragma unroll
            for (int q = 0; q < 4; q++) acc[mt][nt][q] = 0.f;

    int r = tid >> 1, c0 = (tid & 1) * 32;            // convert: 2 threads/row, 32 cols each
    int grow = row0 + r;
    const float* Arow = ((LAYER == 1) ? g_A : g_Y) + (size_t)grow * DD;
    const __nv_bfloat16* Wh = g_Whi[LAYER - 1] + r * DD;
    const __nv_bfloat16* Wl = g_Wlo[LAYER - 1] + r * DD;

#pragma unroll 1
    for (int kc = 0; kc < 2; kc++) {
        int kb = kc * 64;
        // ---- chunk load/convert ----
        {
            char* psm = dynsm;
#pragma unroll 4
            for (int cc = 0; cc < 32; cc += 4) {
                int cl = c0 + cc;            // local col in chunk
                int c = kb + cl;             // global k
                float4 v = make_float4(0.f, 0.f, 0.f, 0.f);
                if (grow < Nn) v = *reinterpret_cast<const float4*>(Arow + c);
                if (LAYER == 2) {
                    v.x = fmaxf(fmaf(v.x, s_s[c + 0], s_t[c + 0]), 0.f);
                    v.y = fmaxf(fmaf(v.y, s_s[c + 1], s_t[c + 1]), 0.f);
                    v.z = fmaxf(fmaf(v.z, s_s[c + 2], s_t[c + 2]), 0.f);
                    v.w = fmaxf(fmaf(v.w, s_s[c + 3], s_t[c + 3]), 0.f);
                }
                __nv_bfloat162 h0 = __floats2bfloat162_rn(v.x, v.y);
                __nv_bfloat162 h1 = __floats2bfloat162_rn(v.z, v.w);
                __nv_bfloat162 l0 = __floats2bfloat162_rn(v.x - __low2float(h0), v.y - __high2float(h0));
                __nv_bfloat162 l1 = __floats2bfloat162_rn(v.z - __low2float(h1), v.w - __high2float(h1));
                uint32_t off = (uint32_t)(r * LDC + cl) * 2;
                *reinterpret_cast<uint2*>(psm + off) =
                    make_uint2(reinterpret_cast<uint32_t&>(h0), reinterpret_cast<uint32_t&>(h1));
                *reinterpret_cast<uint2*>(psm + 18432 + off) =
                    make_uint2(reinterpret_cast<uint32_t&>(l0), reinterpret_cast<uint32_t&>(l1));
                *reinterpret_cast<uint2*>(psm + 36864 + off) = *reinterpret_cast<const uint2*>(Wh + c);
                *reinterpret_cast<uint2*>(psm + 55296 + off) = *reinterpret_cast<const uint2*>(Wl + c);
            }
        }
        __syncthreads();

        // ---- chunk mma: D += Ah*Wh + Ah*Wl + Al*Wh ----
#pragma unroll
        for (int kk = 0; kk < 4; kk++) {
            int k0 = kk * 16;
            uint32_t ah[2][4], al[2][4];
#pragma unroll
            for (int mt = 0; mt < 2; mt++) {
                uint32_t aoff = (uint32_t)((aRow + mt * 16) * LDC + k0 + aKh) * 2;
                ldx4(ah[mt], AHI + aoff);
                ldx4(al[mt], ALO + aoff);
            }
#pragma unroll
            for (int ntp = 0; ntp < 4; ntp++) {
                uint32_t boff = (uint32_t)((bRow + ntp * 16) * LDC + k0 + bKh) * 2;
                uint32_t bh[4], bl[4];
                ldx4(bh, WHI + boff);
                ldx4(bl, WLO + boff);
#pragma unroll
                for (int mt = 0; mt < 2; mt++) {
                    mma16816(acc[mt][2 * ntp + 0], ah[mt], bh[0], bh[1]);
                    mma16816(acc[mt][2 * ntp + 1], ah[mt], bh[2], bh[3]);
                    mma16816(acc[mt][2 * ntp + 0], ah[mt], bl[0], bl[1]);
                    mma16816(acc[mt][2 * ntp + 1], ah[mt], bl[2], bl[3]);
                    mma16816(acc[mt][2 * ntp + 0], al[mt], bh[0], bh[1]);
                    mma16816(acc[mt][2 * ntp + 1], al[mt], bh[2], bh[3]);
                }
            }
        }
        __syncthreads();
    }

    // ---- epilogue: bias + store + fused BN stats ----
#pragma unroll
    for (int mt = 0; mt < 2; mt++) {
        int r0 = row0 + warp_m * 32 + mt * 16 + (lane >> 2);
        int r1 = r0 + 8;
#pragma unroll
        for (int nt = 0; nt < 8; nt++) {
            int c = warp_n * 64 + nt * 8 + (lane & 3) * 2;
            float bx = s_bias[c], by = s_bias[c + 1];
            float v00 = acc[mt][nt][0] + bx, v01 = acc[mt][nt][1] + by;
            float v10 = acc[mt][nt][2] + bx, v11 = acc[mt][nt][3] + by;
            float cs0 = 0.f, cs1 = 0.f, cq0 = 0.f, cq1 = 0.f;
            if (r0 < Nn) {
                *reinterpret_cast<float2*>(&g_Y[(size_t)r0 * DD + c]) = make_float2(v00, v01);
                cs0 += v00; cs1 += v01;
                cq0 = fmaf(v00, v00, cq0); cq1 = fmaf(v01, v01, cq1);
            }
            if (r1 < Nn) {
                *reinterpret_cast<float2*>(&g_Y[(size_t)r1 * DD + c]) = make_float2(v10, v11);
                cs0 += v10; cs1 += v11;
                cq0 = fmaf(v10, v10, cq0); cq1 = fmaf(v11, v11, cq1);
            }
#pragma unroll
            for (int m = 4; m <= 16; m <<= 1) {
                cs0 += __shfl_xor_sync(0xffffffffu, cs0, m);
                cs1 += __shfl_xor_sync(0xffffffffu, cs1, m);
                cq0 += __shfl_xor_sync(0xffffffffu, cq0, m);
                cq1 += __shfl_xor_sync(0xffffffffu, cq1, m);
            }
            if ((lane >> 2) == 0) {
                atomicAdd(&s_sum[c], cs0);     atomicAdd(&s_sum[c + 1], cs1);
                atomicAdd(&s_sq[c], cq0);      atomicAdd(&s_sq[c + 1], cq1);
            }
        }
    }
    __syncthreads();
    if (tid < DD) {
        float* osum = g_stat + (LAYER == 1 ? 0 : 2 * DD);
        atomicAdd(&osum[tid], s_sum[tid]);
        atomicAdd(&osum[DD + tid], s_sq[tid]);
    }
}

// ---------------------------------------------------------------------------
template <int LAYER>
__global__ void k_bn(const float* __restrict__ g, const float* __restrict__ beta, int N) {
    int j = threadIdx.x;
    const float* sum = g_stat + (LAYER == 1 ? 0 : 2 * DD);
    float invN = 1.0f / (float)N;
    float mean = sum[j] * invN;
    float var  = sum[DD + j] * invN - mean * mean;
    float sc = __ldg(&g[j]) * rsqrtf(var + 1e-5f);
    float* outS = g_stat + (LAYER == 1 ? 4 * DD : 6 * DD);
    outS[j] = sc;
    outS[DD + j] = __ldg(&beta[j]) - mean * sc;
}

// ---------------------------------------------------------------------------
__global__ void k_final(float* __restrict__ out, int n4) {
    const float4* Y4 = reinterpret_cast<const float4*>(g_Y);
    float4* o4 = reinterpret_cast<float4*>(out);
    for (int i = blockIdx.x * blockDim.x + threadIdx.x; i < n4; i += gridDim.x * blockDim.x) {
        int cb = (i & 31) * 4;
        float4 y = Y4[i];
        float4 r;
        r.x = fmaxf(fmaf(y.x, g_stat[6 * DD + cb + 0], g_stat[7 * DD + cb + 0]), 0.f);
        r.y = fmaxf(fmaf(y.y, g_stat[6 * DD + cb + 1], g_stat[7 * DD + cb + 1]), 0.f);
        r.z = fmaxf(fmaf(y.z, g_stat[6 * DD + cb + 2], g_stat[7 * DD + cb + 2]), 0.f);
        r.w = fmaxf(fmaf(y.w, g_stat[6 * DD + cb + 3], g_stat[7 * DD + cb + 3]), 0.f);
        o4[i] = r;
    }
}

// ---------------------------------------------------------------------------
extern "C" void kernel_launch(void* const* d_in, const int* in_sizes, int n_in,
                              void* d_out, int out_size) {
    const float* x   = (const float*)d_in[0];
    const int*   ei  = (const int*)d_in[1];
    const float* eps = (const float*)d_in[2];
    const float* W1  = (const float*)d_in[3];
    const float* b1  = (const float*)d_in[4];
    const float* g1  = (const float*)d_in[5];
    const float* be1 = (const float*)d_in[6];
    const float* W2  = (const float*)d_in[7];
    const float* b2  = (const float*)d_in[8];
    const float* g2  = (const float*)d_in[9];
    const float* be2 = (const float*)d_in[10];

    int N  = in_sizes[0] / DD;
    int E  = in_sizes[1] / 2;
    int n4 = N * (DD / 4);
    int gb = (N + 127) / 128;
    int nblk = (N + 511) / 512;
    int eb = (E + 255) / 256;

    const int DYN = 4 * 128 * LDC * 2;   // 73728 B
    cudaFuncSetAttribute((const void*)k_gemm_tc<1>, cudaFuncAttributeMaxDynamicSharedMemorySize, DYN);
    cudaFuncSetAttribute((const void*)k_gemm_tc<2>, cudaFuncAttributeMaxDynamicSharedMemorySize, DYN);

    k_detect<<<1, 256>>>(ei, E);
    k_zero<<<400, 256>>>(N);
    k_prep<<<128, 256>>>(W1, W2);
    k_hist<<<eb, 256>>>(ei, E);
    k_scanA<<<nblk, 256>>>(N);
    k_scanB<<<1, 256>>>(nblk);
    k_scanC<<<nblk, 256>>>(N);
    k_fill<<<eb, 256>>>(ei, E);
    k_aggr<<<(N * 32 + 255) / 256, 256>>>((const float4*)x, eps, N, E);
    k_gemm_tc<1><<<gb, 256, DYN>>>(b1, N);
    k_bn<1><<<1, DD>>>(g1, be1, N);
    k_gemm_tc<2><<<gb, 256, DYN>>>(b2, N);
    k_bn<2><<<1, DD>>>(g2, be2, N);
    k_final<<<2048, 256>>>((float*)d_out, n4);
}

// round 9
// speedup vs baseline: 1.3574x; 1.3574x over previous
#include <cuda_runtime.h>
#include <cuda_bf16.h>
#include <cstdint>

#define DD 128
#define MAXN 100000
#define MAXE 655360
#define LDA 136                      // smem tile stride (bf16), conflict-free ldmatrix
#define GGRID 152                    // persistent GEMM grid (1 CTA/SM)

// ---- scratch (no allocs allowed) -------------------------------------------
__device__ __align__(16) float g_A[(size_t)MAXN * DD];   // (1+eps)x + aggr
__device__ __align__(16) float g_Y[(size_t)MAXN * DD];   // layer outputs
// [0:128) sum1 [128:256) sq1 [256:384) sum2 [384:512) sq2
// [512:640) s1 [640:768) t1 [768:896) s2 [896:1024) t2
__device__ float g_stat[8 * DD];
__device__ int   g_i64flag;
__device__ __align__(16) __nv_bfloat16 g_Whi[2][DD * DD];
__device__ __align__(16) __nv_bfloat16 g_Wlo[2][DD * DD];
// CSR scratch
__device__ int g_cnt[MAXN + 1];
__device__ int g_off[MAXN + 1];
__device__ int g_cur[MAXN];
__device__ int g_srcid[MAXE];
__device__ int g_blksum[256];
__device__ int g_blkoff[256];

#define SMEMU32(p) ((uint32_t)__cvta_generic_to_shared(p))

__device__ __forceinline__ void ldx4(uint32_t* r, uint32_t addr) {
    asm volatile("ldmatrix.sync.aligned.m8n8.x4.shared.b16 {%0,%1,%2,%3}, [%4];"
                 : "=r"(r[0]), "=r"(r[1]), "=r"(r[2]), "=r"(r[3]) : "r"(addr));
}
__device__ __forceinline__ void mma16816(float* c, const uint32_t* a, uint32_t b0, uint32_t b1) {
    asm volatile("mma.sync.aligned.m16n8k16.row.col.f32.bf16.bf16.f32 "
                 "{%0,%1,%2,%3}, {%4,%5,%6,%7}, {%8,%9}, {%0,%1,%2,%3};"
                 : "+f"(c[0]), "+f"(c[1]), "+f"(c[2]), "+f"(c[3])
                 : "r"(a[0]), "r"(a[1]), "r"(a[2]), "r"(a[3]), "r"(b0), "r"(b1));
}
__device__ __forceinline__ float4 ldg4v(const float* p) {
    float4 v;
    asm volatile("ld.global.nc.v4.f32 {%0,%1,%2,%3}, [%4];"
                 : "=f"(v.x), "=f"(v.y), "=f"(v.z), "=f"(v.w) : "l"(p));
    return v;
}

// ---------------------------------------------------------------------------
__global__ void k_detect(const int* __restrict__ w, int E) {
    __shared__ int s_or;
    if (threadIdx.x == 0) s_or = 0;
    __syncthreads();
    int total = 2 * E;
    int step = total / 4096; if (step < 2) step = 2;
    int acc = 0;
    for (int i = threadIdx.x; i < 4096; i += blockDim.x) {
        long long idx = ((long long)i * step) | 1;
        if (idx < total) acc |= w[idx];
    }
    atomicOr(&s_or, acc);
    __syncthreads();
    if (threadIdx.x == 0) g_i64flag = (s_or == 0) ? 1 : 0;
}

// ---------------------------------------------------------------------------
__global__ void k_zero(int Nn) {
    if (blockIdx.x == 0 && threadIdx.x < 256) {
        g_stat[threadIdx.x] = 0.0f;
        g_stat[threadIdx.x + 256] = 0.0f;
    }
    for (int i = blockIdx.x * blockDim.x + threadIdx.x; i < Nn; i += gridDim.x * blockDim.x)
        g_cnt[i] = 0;
}

// ---------------------------------------------------------------------------
__global__ void k_hist(const int* __restrict__ w, int E) {
    int e = blockIdx.x * blockDim.x + threadIdx.x;
    if (e >= E) return;
    int d = g_i64flag ? __ldg(&w[2 * (E + e)]) : __ldg(&w[E + e]);
    atomicAdd(&g_cnt[d], 1);
}

// ---- 3-stage exclusive scan of g_cnt -> g_off ------------------------------
__global__ void k_scanA(int Nn) {
    __shared__ int sm[256];
    int b = blockIdx.x, t = threadIdx.x;
    int base = b * 512;
    int v = 0;
    if (base + t < Nn)       v += g_cnt[base + t];
    if (base + t + 256 < Nn) v += g_cnt[base + t + 256];
    sm[t] = v; __syncthreads();
    for (int o = 128; o > 0; o >>= 1) { if (t < o) sm[t] += sm[t + o]; __syncthreads(); }
    if (t == 0) g_blksum[b] = sm[0];
}
__global__ void k_scanB(int nblk) {
    __shared__ int sm[256];
    int t = threadIdx.x;
    int v = (t < nblk) ? g_blksum[t] : 0;
    sm[t] = v; __syncthreads();
    for (int o = 1; o < 256; o <<= 1) {
        int a = (t >= o) ? sm[t - o] : 0;
        __syncthreads(); sm[t] += a; __syncthreads();
    }
    if (t < nblk) g_blkoff[t] = sm[t] - v;
}
__global__ void k_scanC(int Nn) {
    __shared__ int sm[256];
    int b = blockIdx.x, t = threadIdx.x;
    int i0 = b * 512 + 2 * t, i1 = i0 + 1;
    int c0 = (i0 < Nn) ? g_cnt[i0] : 0;
    int c1 = (i1 < Nn) ? g_cnt[i1] : 0;
    int v = c0 + c1;
    sm[t] = v; __syncthreads();
    for (int o = 1; o < 256; o <<= 1) {
        int a = (t >= o) ? sm[t - o] : 0;
        __syncthreads(); sm[t] += a; __syncthreads();
    }
    int excl = sm[t] - v + g_blkoff[b];
    if (i0 < Nn) { g_off[i0] = excl;      g_cur[i0] = excl; }
    if (i1 < Nn) { g_off[i1] = excl + c0; g_cur[i1] = excl + c0; }
}

// ---------------------------------------------------------------------------
__global__ void k_fill(const int* __restrict__ w, int E) {
    int e = blockIdx.x * blockDim.x + threadIdx.x;
    if (e >= E) return;
    int s, d;
    if (g_i64flag) { s = __ldg(&w[2 * e]); d = __ldg(&w[2 * (E + e)]); }
    else           { s = __ldg(&w[e]);     d = __ldg(&w[E + e]); }
    int p = atomicAdd(&g_cur[d], 1);
    g_srcid[p] = s;
}

// ---------------------------------------------------------------------------
// One warp per node: A[d] = (1+eps)*x[d] + sum_{e in bucket(d)} x[src(e)]
__global__ __launch_bounds__(256) void k_aggr(const float4* __restrict__ x,
                                              const float* __restrict__ eps, int Nn, int E) {
    int gw = (blockIdx.x * blockDim.x + threadIdx.x) >> 5;
    int lane = threadIdx.x & 31;
    if (gw >= Nn) return;
    float e = 1.0f + __ldg(eps);
    int beg = g_off[gw];
    int end = (gw + 1 < Nn) ? g_off[gw + 1] : E;
    float4 a = __ldg(&x[(size_t)gw * 32 + lane]);
    float4 acc = make_float4(a.x * e, a.y * e, a.z * e, a.w * e);
    int i = beg;
    for (; i + 3 < end; i += 4) {
        int s0 = __ldg(&g_srcid[i + 0]), s1 = __ldg(&g_srcid[i + 1]);
        int s2 = __ldg(&g_srcid[i + 2]), s3 = __ldg(&g_srcid[i + 3]);
        float4 v0 = __ldg(&x[(size_t)s0 * 32 + lane]);
        float4 v1 = __ldg(&x[(size_t)s1 * 32 + lane]);
        float4 v2 = __ldg(&x[(size_t)s2 * 32 + lane]);
        float4 v3 = __ldg(&x[(size_t)s3 * 32 + lane]);
        acc.x += v0.x + v1.x + v2.x + v3.x;
        acc.y += v0.y + v1.y + v2.y + v3.y;
        acc.z += v0.z + v1.z + v2.z + v3.z;
        acc.w += v0.w + v1.w + v2.w + v3.w;
    }
    for (; i < end; i++) {
        int s = __ldg(&g_srcid[i]);
        float4 v = __ldg(&x[(size_t)s * 32 + lane]);
        acc.x += v.x; acc.y += v.y; acc.z += v.z; acc.w += v.w;
    }
    *reinterpret_cast<float4*>(&g_A[(size_t)gw * DD + lane * 4]) = acc;
}

// ---------------------------------------------------------------------------
__global__ void k_prep(const float* __restrict__ W1, const float* __restrict__ W2) {
    int i = blockIdx.x * blockDim.x + threadIdx.x;
    if (i >= 2 * DD * DD) return;
    int layer = i >> 14, j = i & (DD * DD - 1);
    float v = (layer == 0) ? W1[j] : W2[j];
    __nv_bfloat16 h = __float2bfloat16_rn(v);
    g_Whi[layer][j] = h;
    g_Wlo[layer][j] = __float2bfloat16_rn(v - __bfloat162float(h));
}

// ---------------------------------------------------------------------------
// PERSISTENT mma.sync GEMM. Grid=GGRID CTAs, each loops tiles t, t+GGRID, ...
// W hi/lo resident in smem; A double-buffered; prefetch A(t+1) during mma(t).
// dynsm: W_hi @0, W_lo @34816, Abuf0(hi,lo) @69632, Abuf1(hi,lo) @139264
template <int LAYER>
__global__ __launch_bounds__(256) void k_gemm_tc(const float* __restrict__ bias,
                                                 int Nn, int nTiles) {
    extern __shared__ char dynsm[];
    __shared__ float s_bias[DD];
    __shared__ float s_s[DD], s_t[DD];
    __shared__ float s_sum[DD], s_sq[DD];

    const uint32_t sbase = SMEMU32(dynsm);
    const uint32_t WHI = sbase, WLO = sbase + 34816;

    int tid = threadIdx.x, wid = tid >> 5, lane = tid & 31;
    if (tid < DD) {
        s_bias[tid] = __ldg(&bias[tid]);
        s_sum[tid] = 0.f; s_sq[tid] = 0.f;
        if (LAYER == 2) { s_s[tid] = g_stat[4 * DD + tid]; s_t[tid] = g_stat[5 * DD + tid]; }
    }

    int r = tid >> 1, c0 = (tid & 1) * 64;     // load/convert mapping: 2 threads/row
    const float* Abase = (LAYER == 1) ? g_A : g_Y;

    // ---- W hi/lo -> smem (once) ----
    {
        const __nv_bfloat16* Wh = g_Whi[LAYER - 1] + r * DD;
        const __nv_bfloat16* Wl = g_Wlo[LAYER - 1] + r * DD;
        char* psm = dynsm;
#pragma unroll
        for (int i2 = 0; i2 < 16; i2++) {
            int c = c0 + i2 * 4;
            uint32_t off = (uint32_t)(r * LDA + c) * 2;
            *reinterpret_cast<uint2*>(psm + off)        = *reinterpret_cast<const uint2*>(Wh + c);
            *reinterpret_cast<uint2*>(psm + 34816 + off) = *reinterpret_cast<const uint2*>(Wl + c);
        }
    }
    __syncthreads();   // s_s/s_t (+W) visible

    // mma lane mapping
    int warp_m = wid & 3, warp_n = wid >> 2;
    int aRow = warp_m * 32 + (lane & 15);
    int aKh  = (lane >> 4) * 8;
    int bRow = warp_n * 64 + (lane & 7) + ((lane >> 4) & 1) * 8;
    int bKh  = ((lane >> 3) & 1) * 8;

    float4 va[16];
    int t = blockIdx.x;

    // prologue: load + convert tile t into buf 0
    if (t < nTiles) {
        int grow = t * 128 + r;
        const float* Arow = Abase + (size_t)grow * DD;
#pragma unroll
        for (int i2 = 0; i2 < 16; i2++)
            va[i2] = (grow < Nn) ? ldg4v(Arow + c0 + i2 * 4) : make_float4(0.f, 0.f, 0.f, 0.f);
        char* pAhi = dynsm + 69632;
#pragma unroll
        for (int i2 = 0; i2 < 16; i2++) {
            int c = c0 + i2 * 4;
            float4 v = va[i2];
            if (LAYER == 2) {
                v.x = fmaxf(fmaf(v.x, s_s[c + 0], s_t[c + 0]), 0.f);
                v.y = fmaxf(fmaf(v.y, s_s[c + 1], s_t[c + 1]), 0.f);
                v.z = fmaxf(fmaf(v.z, s_s[c + 2], s_t[c + 2]), 0.f);
                v.w = fmaxf(fmaf(v.w, s_s[c + 3], s_t[c + 3]), 0.f);
            }
            __nv_bfloat162 h0 = __floats2bfloat162_rn(v.x, v.y);
            __nv_bfloat162 h1 = __floats2bfloat162_rn(v.z, v.w);
            __nv_bfloat162 l0 = __floats2bfloat162_rn(v.x - __low2float(h0), v.y - __high2float(h0));
            __nv_bfloat162 l1 = __floats2bfloat162_rn(v.z - __low2float(h1), v.w - __high2float(h1));
            uint32_t off = (uint32_t)(r * LDA + c) * 2;
            *reinterpret_cast<uint2*>(pAhi + off) =
                make_uint2(reinterpret_cast<uint32_t&>(h0), reinterpret_cast<uint32_t&>(h1));
            *reinterpret_cast<uint2*>(pAhi + 34816 + off) =
                make_uint2(reinterpret_cast<uint32_t&>(l0), reinterpret_cast<uint32_t&>(l1));
        }
    }
    __syncthreads();

    int buf = 0;
    while (t < nTiles) {
        int tn = t + GGRID;
        // ---- prefetch A(tn) into regs (issued before mma; hidden behind it) ----
        if (tn < nTiles) {
            int grow = tn * 128 + r;
            const float* Arow = Abase + (size_t)grow * DD;
#pragma unroll
            for (int i2 = 0; i2 < 16; i2++)
                va[i2] = (grow < Nn) ? ldg4v(Arow + c0 + i2 * 4) : make_float4(0.f, 0.f, 0.f, 0.f);
        }

        // ---- mma on buf ----
        uint32_t AHIb = sbase + 69632 + (uint32_t)buf * 69632;
        uint32_t ALOb = AHIb + 34816;
        float acc[2][8][4];
#pragma unroll
        for (int mt = 0; mt < 2; mt++)
#pragma unroll
            for (int nt = 0; nt < 8; nt++)
#pragma unroll
                for (int q = 0; q < 4; q++) acc[mt][nt][q] = 0.f;

#pragma unroll
        for (int kk = 0; kk < 8; kk++) {
            int k0 = kk * 16;
            uint32_t ah[2][4], al[2][4];
#pragma unroll
            for (int mt = 0; mt < 2; mt++) {
                uint32_t aoff = (uint32_t)((aRow + mt * 16) * LDA + k0 + aKh) * 2;
                ldx4(ah[mt], AHIb + aoff);
                ldx4(al[mt], ALOb + aoff);
            }
#pragma unroll
            for (int ntp = 0; ntp < 4; ntp++) {
                uint32_t boff = (uint32_t)((bRow + ntp * 16) * LDA + k0 + bKh) * 2;
                uint32_t bh[4], bl[4];
                ldx4(bh, WHI + boff);
                ldx4(bl, WLO + boff);
#pragma unroll
                for (int mt = 0; mt < 2; mt++) {
                    mma16816(acc[mt][2 * ntp + 0], ah[mt], bh[0], bh[1]);
                    mma16816(acc[mt][2 * ntp + 1], ah[mt], bh[2], bh[3]);
                    mma16816(acc[mt][2 * ntp + 0], ah[mt], bl[0], bl[1]);
                    mma16816(acc[mt][2 * ntp + 1], ah[mt], bl[2], bl[3]);
                    mma16816(acc[mt][2 * ntp + 0], al[mt], bh[0], bh[1]);
                    mma16816(acc[mt][2 * ntp + 1], al[mt], bh[2], bh[3]);
                }
            }
        }

        // ---- epilogue: bias + store + BN stats (smem accum) ----
        int row0 = t * 128;
#pragma unroll
        for (int mt = 0; mt < 2; mt++) {
            int r0 = row0 + warp_m * 32 + mt * 16 + (lane >> 2);
            int r1 = r0 + 8;
#pragma unroll
            for (int nt = 0; nt < 8; nt++) {
                int c = warp_n * 64 + nt * 8 + (lane & 3) * 2;
                float bx = s_bias[c], by = s_bias[c + 1];
                float v00 = acc[mt][nt][0] + bx, v01 = acc[mt][nt][1] + by;
                float v10 = acc[mt][nt][2] + bx, v11 = acc[mt][nt][3] + by;
                float cs0 = 0.f, cs1 = 0.f, cq0 = 0.f, cq1 = 0.f;
                if (r0 < Nn) {
                    *reinterpret_cast<float2*>(&g_Y[(size_t)r0 * DD + c]) = make_float2(v00, v01);
                    cs0 += v00; cs1 += v01;
                    cq0 = fmaf(v00, v00, cq0); cq1 = fmaf(v01, v01, cq1);
                }
                if (r1 < Nn) {
                    *reinterpret_cast<float2*>(&g_Y[(size_t)r1 * DD + c]) = make_float2(v10, v11);
                    cs0 += v10; cs1 += v11;
                    cq0 = fmaf(v10, v10, cq0); cq1 = fmaf(v11, v11, cq1);
                }
#pragma unroll
                for (int m = 4; m <= 16; m <<= 1) {
                    cs0 += __shfl_xor_sync(0xffffffffu, cs0, m);
                    cs1 += __shfl_xor_sync(0xffffffffu, cs1, m);
                    cq0 += __shfl_xor_sync(0xffffffffu, cq0, m);
                    cq1 += __shfl_xor_sync(0xffffffffu, cq1, m);
                }
                if ((lane >> 2) == 0) {
                    atomicAdd(&s_sum[c], cs0);     atomicAdd(&s_sum[c + 1], cs1);
                    atomicAdd(&s_sq[c], cq0);      atomicAdd(&s_sq[c + 1], cq1);
                }
            }
        }

        // ---- convert prefetched A(tn) into other buffer ----
        if (tn < nTiles) {
            char* pAhi = dynsm + 69632 + (buf ^ 1) * 69632;
#pragma unroll
            for (int i2 = 0; i2 < 16; i2++) {
                int c = c0 + i2 * 4;
                float4 v = va[i2];
                if (LAYER == 2) {
                    v.x = fmaxf(fmaf(v.x, s_s[c + 0], s_t[c + 0]), 0.f);
                    v.y = fmaxf(fmaf(v.y, s_s[c + 1], s_t[c + 1]), 0.f);
                    v.z = fmaxf(fmaf(v.z, s_s[c + 2], s_t[c + 2]), 0.f);
                    v.w = fmaxf(fmaf(v.w, s_s[c + 3], s_t[c + 3]), 0.f);
                }
                __nv_bfloat162 h0 = __floats2bfloat162_rn(v.x, v.y);
                __nv_bfloat162 h1 = __floats2bfloat162_rn(v.z, v.w);
                __nv_bfloat162 l0 = __floats2bfloat162_rn(v.x - __low2float(h0), v.y - __high2float(h0));
                __nv_bfloat162 l1 = __floats2bfloat162_rn(v.z - __low2float(h1), v.w - __high2float(h1));
                uint32_t off = (uint32_t)(r * LDA + c) * 2;
                *reinterpret_cast<uint2*>(pAhi + off) =
                    make_uint2(reinterpret_cast<uint32_t&>(h0), reinterpret_cast<uint32_t&>(h1));
                *reinterpret_cast<uint2*>(pAhi + 34816 + off) =
                    make_uint2(reinterpret_cast<uint32_t&>(l0), reinterpret_cast<uint32_t&>(l1));
            }
        }
        __syncthreads();
        buf ^= 1;
        t = tn;
    }

    // ---- flush BN stats once per CTA ----
    if (tid < DD) {
        float* osum = g_stat + (LAYER == 1 ? 0 : 2 * DD);
        atomicAdd(&osum[tid], s_sum[tid]);
        atomicAdd(&osum[DD + tid], s_sq[tid]);
    }
}

// ---------------------------------------------------------------------------
template <int LAYER>
__global__ void k_bn(const float* __restrict__ g, const float* __restrict__ beta, int N) {
    int j = threadIdx.x;
    const float* sum = g_stat + (LAYER == 1 ? 0 : 2 * DD);
    float invN = 1.0f / (float)N;
    float mean = sum[j] * invN;
    float var  = sum[DD + j] * invN - mean * mean;
    float sc = __ldg(&g[j]) * rsqrtf(var + 1e-5f);
    float* outS = g_stat + (LAYER == 1 ? 4 * DD : 6 * DD);
    outS[j] = sc;
    outS[DD + j] = __ldg(&beta[j]) - mean * sc;
}

// ---------------------------------------------------------------------------
__global__ void k_final(float* __restrict__ out, int n4) {
    const float4* Y4 = reinterpret_cast<const float4*>(g_Y);
    float4* o4 = reinterpret_cast<float4*>(out);
    for (int i = blockIdx.x * blockDim.x + threadIdx.x; i < n4; i += gridDim.x * blockDim.x) {
        int cb = (i & 31) * 4;
        float4 y = Y4[i];
        float4 r;
        r.x = fmaxf(fmaf(y.x, g_stat[6 * DD + cb + 0], g_stat[7 * DD + cb + 0]), 0.f);
        r.y = fmaxf(fmaf(y.y, g_stat[6 * DD + cb + 1], g_stat[7 * DD + cb + 1]), 0.f);
        r.z = fmaxf(fmaf(y.z, g_stat[6 * DD + cb + 2], g_stat[7 * DD + cb + 2]), 0.f);
        r.w = fmaxf(fmaf(y.w, g_stat[6 * DD + cb + 3], g_stat[7 * DD + cb + 3]), 0.f);
        o4[i] = r;
    }
}

// ---------------------------------------------------------------------------
extern "C" void kernel_launch(void* const* d_in, const int* in_sizes, int n_in,
                              void* d_out, int out_size) {
    const float* x   = (const float*)d_in[0];
    const int*   ei  = (const int*)d_in[1];
    const float* eps = (const float*)d_in[2];
    const float* W1  = (const float*)d_in[3];
    const float* b1  = (const float*)d_in[4];
    const float* g1  = (const float*)d_in[5];
    const float* be1 = (const float*)d_in[6];
    const float* W2  = (const float*)d_in[7];
    const float* b2  = (const float*)d_in[8];
    const float* g2  = (const float*)d_in[9];
    const float* be2 = (const float*)d_in[10];

    int N  = in_sizes[0] / DD;
    int E  = in_sizes[1] / 2;
    int n4 = N * (DD / 4);
    int gb = (N + 127) / 128;            // tiles
    int nblk = (N + 511) / 512;
    int eb = (E + 255) / 256;

    const int DYN = 3 * 69632;           // W(hi+lo) + 2 A buffers = 208896 B
    cudaFuncSetAttribute((const void*)k_gemm_tc<1>, cudaFuncAttributeMaxDynamicSharedMemorySize, DYN);
    cudaFuncSetAttribute((const void*)k_gemm_tc<2>, cudaFuncAttributeMaxDynamicSharedMemorySize, DYN);

    int ggrid = gb < GGRID ? gb : GGRID;

    k_detect<<<1, 256>>>(ei, E);
    k_zero<<<400, 256>>>(N);
    k_prep<<<128, 256>>>(W1, W2);
    k_hist<<<eb, 256>>>(ei, E);
    k_scanA<<<nblk, 256>>>(N);
    k_scanB<<<1, 256>>>(nblk);
    k_scanC<<<nblk, 256>>>(N);
    k_fill<<<eb, 256>>>(ei, E);
    k_aggr<<<(N * 32 + 255) / 256, 256>>>((const float4*)x, eps, N, E);
    k_gemm_tc<1><<<ggrid, 256, DYN>>>(b1, N, gb);
    k_bn<1><<<1, DD>>>(g1, be1, N);
    k_gemm_tc<2><<<ggrid, 256, DYN>>>(b2, N, gb);
    k_bn<2><<<1, DD>>>(g2, be2, N);
    k_final<<<2048, 256>>>((float*)d_out, n4);
}

// round 10
// speedup vs baseline: 1.4651x; 1.0793x over previous
#include <cuda_runtime.h>
#include <cuda_bf16.h>
#include <cstdint>

#define DD 128
#define MAXN 100000
#define MAXE 655360
#define LDA 136                      // bf16 tile stride, conflict-free ldmatrix
#define RSTR 132                     // raw fp32 staging stride (floats)
#define GGRID 152                    // persistent GEMM grid (1 CTA/SM)

// smem layout (dynamic) for gemm:
#define OFF_WHI 0
#define OFF_WLO 34816
#define OFF_AHI 69632
#define OFF_ALO 104448
#define OFF_RAW 139264
#define DYN_GEMM (139264 + 128 * RSTR * 4)   // 206848 B

// ---- scratch (no allocs allowed) -------------------------------------------
__device__ __align__(16) float g_A[(size_t)MAXN * DD];
__device__ __align__(16) float g_Y[(size_t)MAXN * DD];
// [0:128) sum1 [128:256) sq1 [256:384) sum2 [384:512) sq2
// [512:640) s1 [640:768) t1 [768:896) s2 [896:1024) t2
__device__ float g_stat[8 * DD];
__device__ int   g_i64flag;
__device__ __align__(16) __nv_bfloat16 g_Whi[2][DD * DD];
__device__ __align__(16) __nv_bfloat16 g_Wlo[2][DD * DD];
// CSR scratch
__device__ int g_cnt[MAXN + 1];
__device__ int g_off[MAXN + 1];
__device__ int g_cur[MAXN];
__device__ int g_srcid[MAXE];
__device__ int g_blksum[256];

#define SMEMU32(p) ((uint32_t)__cvta_generic_to_shared(p))

__device__ __forceinline__ void ldx4(uint32_t* r, uint32_t addr) {
    asm volatile("ldmatrix.sync.aligned.m8n8.x4.shared.b16 {%0,%1,%2,%3}, [%4];"
                 : "=r"(r[0]), "=r"(r[1]), "=r"(r[2]), "=r"(r[3]) : "r"(addr));
}
__device__ __forceinline__ void mma16816(float* c, const uint32_t* a, uint32_t b0, uint32_t b1) {
    asm volatile("mma.sync.aligned.m16n8k16.row.col.f32.bf16.bf16.f32 "
                 "{%0,%1,%2,%3}, {%4,%5,%6,%7}, {%8,%9}, {%0,%1,%2,%3};"
                 : "+f"(c[0]), "+f"(c[1]), "+f"(c[2]), "+f"(c[3])
                 : "r"(a[0]), "r"(a[1]), "r"(a[2]), "r"(a[3]), "r"(b0), "r"(b1));
}
__device__ __forceinline__ void cpasync16(uint32_t dst, const float* src, int sz) {
    asm volatile("cp.async.cg.shared.global [%0], [%1], 16, %2;"
                 :: "r"(dst), "l"(src), "r"(sz) : "memory");
}
#define CP_COMMIT() asm volatile("cp.async.commit_group;" ::: "memory")
#define CP_WAIT0()  asm volatile("cp.async.wait_group 0;" ::: "memory")

// ---------------------------------------------------------------------------
// setup: dtype detect (block 0) + zero cnt/stat + W hi/lo split
__global__ void k_setup(const int* __restrict__ w, int E, int Nn,
                        const float* __restrict__ W1, const float* __restrict__ W2) {
    int stride = gridDim.x * blockDim.x;
    int gtid = blockIdx.x * blockDim.x + threadIdx.x;
    if (blockIdx.x == 0) {
        __shared__ int s_or;
        if (threadIdx.x == 0) s_or = 0;
        __syncthreads();
        int total = 2 * E;
        int step = total / 4096; if (step < 2) step = 2;
        int acc = 0;
        for (int i = threadIdx.x; i < 4096; i += blockDim.x) {
            long long idx = ((long long)i * step) | 1;
            if (idx < total) acc |= w[idx];
        }
        atomicOr(&s_or, acc);
        __syncthreads();
        if (threadIdx.x == 0) g_i64flag = (s_or == 0) ? 1 : 0;
        g_stat[threadIdx.x] = 0.0f;
        g_stat[threadIdx.x + 256] = 0.0f;
    }
    for (int i = gtid; i < Nn; i += stride) g_cnt[i] = 0;
    for (int i = gtid; i < 2 * DD * DD; i += stride) {
        int layer = i >> 14, j = i & (DD * DD - 1);
        float v = (layer == 0) ? W1[j] : W2[j];
        __nv_bfloat16 h = __float2bfloat16_rn(v);
        g_Whi[layer][j] = h;
        g_Wlo[layer][j] = __float2bfloat16_rn(v - __bfloat162float(h));
    }
}

// ---------------------------------------------------------------------------
__global__ void k_hist(const int* __restrict__ w, int E) {
    int e = blockIdx.x * blockDim.x + threadIdx.x;
    if (e >= E) return;
    int d = g_i64flag ? __ldg(&w[2 * (E + e)]) : __ldg(&w[E + e]);
    atomicAdd(&g_cnt[d], 1);
}

// ---- scan: per-512 block sums, then offsets (blkoff folded into scanC) -----
__global__ void k_scanA(int Nn) {
    __shared__ int sm[256];
    int b = blockIdx.x, t = threadIdx.x;
    int base = b * 512;
    int v = 0;
    if (base + t < Nn)       v += g_cnt[base + t];
    if (base + t + 256 < Nn) v += g_cnt[base + t + 256];
    sm[t] = v; __syncthreads();
    for (int o = 128; o > 0; o >>= 1) { if (t < o) sm[t] += sm[t + o]; __syncthreads(); }
    if (t == 0) g_blksum[b] = sm[0];
}
__global__ void k_scanC(int Nn, int nblk) {
    __shared__ int sm[256];
    __shared__ int s_off;
    int b = blockIdx.x, t = threadIdx.x;
    // block offset = sum_{i<b} blksum[i]
    sm[t] = (t < b) ? g_blksum[t] : 0;
    __syncthreads();
    for (int o = 128; o > 0; o >>= 1) { if (t < o) sm[t] += sm[t + o]; __syncthreads(); }
    if (t == 0) s_off = sm[0];
    __syncthreads();
    // intra-block inclusive scan of pairs
    int i0 = b * 512 + 2 * t, i1 = i0 + 1;
    int c0 = (i0 < Nn) ? g_cnt[i0] : 0;
    int c1 = (i1 < Nn) ? g_cnt[i1] : 0;
    int v = c0 + c1;
    sm[t] = v; __syncthreads();
    for (int o = 1; o < 256; o <<= 1) {
        int a = (t >= o) ? sm[t - o] : 0;
        __syncthreads(); sm[t] += a; __syncthreads();
    }
    int excl = sm[t] - v + s_off;
    if (i0 < Nn) { g_off[i0] = excl;      g_cur[i0] = excl; }
    if (i1 < Nn) { g_off[i1] = excl + c0; g_cur[i1] = excl + c0; }
}

// ---------------------------------------------------------------------------
__global__ void k_fill(const int* __restrict__ w, int E) {
    int e = blockIdx.x * blockDim.x + threadIdx.x;
    if (e >= E) return;
    int s, d;
    if (g_i64flag) { s = __ldg(&w[2 * e]); d = __ldg(&w[2 * (E + e)]); }
    else           { s = __ldg(&w[e]);     d = __ldg(&w[E + e]); }
    int p = atomicAdd(&g_cur[d], 1);
    g_srcid[p] = s;
}

// ---------------------------------------------------------------------------
// One warp per node: A[d] = (1+eps)*x[d] + sum_{e in bucket(d)} x[src(e)]
__global__ __launch_bounds__(256) void k_aggr(const float4* __restrict__ x,
                                              const float* __restrict__ eps, int Nn, int E) {
    int gw = (blockIdx.x * blockDim.x + threadIdx.x) >> 5;
    int lane = threadIdx.x & 31;
    if (gw >= Nn) return;
    float e = 1.0f + __ldg(eps);
    int beg = g_off[gw];
    int end = (gw + 1 < Nn) ? g_off[gw + 1] : E;
    float4 a = __ldg(&x[(size_t)gw * 32 + lane]);
    float4 acc = make_float4(a.x * e, a.y * e, a.z * e, a.w * e);
    int i = beg;
    for (; i + 3 < end; i += 4) {
        int s0 = __ldg(&g_srcid[i + 0]), s1 = __ldg(&g_srcid[i + 1]);
        int s2 = __ldg(&g_srcid[i + 2]), s3 = __ldg(&g_srcid[i + 3]);
        float4 v0 = __ldg(&x[(size_t)s0 * 32 + lane]);
        float4 v1 = __ldg(&x[(size_t)s1 * 32 + lane]);
        float4 v2 = __ldg(&x[(size_t)s2 * 32 + lane]);
        float4 v3 = __ldg(&x[(size_t)s3 * 32 + lane]);
        acc.x += v0.x + v1.x + v2.x + v3.x;
        acc.y += v0.y + v1.y + v2.y + v3.y;
        acc.z += v0.z + v1.z + v2.z + v3.z;
        acc.w += v0.w + v1.w + v2.w + v3.w;
    }
    for (; i < end; i++) {
        int s = __ldg(&g_srcid[i]);
        float4 v = __ldg(&x[(size_t)s * 32 + lane]);
        acc.x += v.x; acc.y += v.y; acc.z += v.z; acc.w += v.w;
    }
    *reinterpret_cast<float4*>(&g_A[(size_t)gw * DD + lane * 4]) = acc;
}

// ---------------------------------------------------------------------------
// PERSISTENT mma.sync GEMM, cp.async-staged A tiles.
// W hi/lo resident in smem; RAW fp32 staging; single bf16 A buffer.
template <int LAYER>
__global__ __launch_bounds__(256) void k_gemm_tc(const float* __restrict__ bias,
                                                 int Nn, int nTiles) {
    extern __shared__ char dynsm[];
    __shared__ float s_bias[DD];
    __shared__ float s_s[DD], s_t[DD];
    __shared__ float s_sum[DD], s_sq[DD];

    const uint32_t sbase = SMEMU32(dynsm);
    const uint32_t WHI = sbase + OFF_WHI, WLO = sbase + OFF_WLO;
    const uint32_t AHI = sbase + OFF_AHI, ALO = sbase + OFF_ALO;
    const uint32_t RAWB = sbase + OFF_RAW;

    int tid = threadIdx.x, wid = tid >> 5, lane = tid & 31;
    if (tid < DD) {
        s_bias[tid] = __ldg(&bias[tid]);
        s_sum[tid] = 0.f; s_sq[tid] = 0.f;
        if (LAYER == 2) { s_s[tid] = g_stat[4 * DD + tid]; s_t[tid] = g_stat[5 * DD + tid]; }
    }

    int r = tid >> 1, c0 = (tid & 1) * 64;
    const float* Abase = (LAYER == 1) ? g_A : g_Y;

    // ---- W hi/lo -> smem (once) ----
    {
        const __nv_bfloat16* Wh = g_Whi[LAYER - 1] + r * DD;
        const __nv_bfloat16* Wl = g_Wlo[LAYER - 1] + r * DD;
        char* psm = dynsm;
#pragma unroll
        for (int i2 = 0; i2 < 16; i2++) {
            int c = c0 + i2 * 4;
            uint32_t off = (uint32_t)(r * LDA + c) * 2;
            *reinterpret_cast<uint2*>(psm + OFF_WHI + off) = *reinterpret_cast<const uint2*>(Wh + c);
            *reinterpret_cast<uint2*>(psm + OFF_WLO + off) = *reinterpret_cast<const uint2*>(Wl + c);
        }
    }
    __syncthreads();   // s_s/s_t/W visible

    int warp_m = wid & 3, warp_n = wid >> 2;
    int aRow = warp_m * 32 + (lane & 15);
    int aKh  = (lane >> 4) * 8;
    int bRow = warp_n * 64 + (lane & 7) + ((lane >> 4) & 1) * 8;
    int bKh  = ((lane >> 3) & 1) * 8;

    // --- helpers (lambdas keep register locality) ---
    auto issueA = [&](int tt) {
        int grow = tt * 128 + r;
        const float* src = Abase + (size_t)grow * DD + c0;
        int sz = (grow < Nn) ? 16 : 0;
        uint32_t dst = RAWB + (uint32_t)(r * RSTR + c0) * 4;
#pragma unroll
        for (int i2 = 0; i2 < 16; i2++) cpasync16(dst + i2 * 16, src + i2 * 4, sz);
        CP_COMMIT();
    };
    auto convertA = [&]() {
        char* psm = dynsm;
#pragma unroll
        for (int i2 = 0; i2 < 16; i2++) {
            int c = c0 + i2 * 4;
            float4 v = *reinterpret_cast<float4*>(psm + OFF_RAW + (uint32_t)(r * RSTR + c) * 4);
            if (LAYER == 2) {
                v.x = fmaxf(fmaf(v.x, s_s[c + 0], s_t[c + 0]), 0.f);
                v.y = fmaxf(fmaf(v.y, s_s[c + 1], s_t[c + 1]), 0.f);
                v.z = fmaxf(fmaf(v.z, s_s[c + 2], s_t[c + 2]), 0.f);
                v.w = fmaxf(fmaf(v.w, s_s[c + 3], s_t[c + 3]), 0.f);
            }
            __nv_bfloat162 h0 = __floats2bfloat162_rn(v.x, v.y);
            __nv_bfloat162 h1 = __floats2bfloat162_rn(v.z, v.w);
            __nv_bfloat162 l0 = __floats2bfloat162_rn(v.x - __low2float(h0), v.y - __high2float(h0));
            __nv_bfloat162 l1 = __floats2bfloat162_rn(v.z - __low2float(h1), v.w - __high2float(h1));
            uint32_t off = (uint32_t)(r * LDA + c) * 2;
            *reinterpret_cast<uint2*>(psm + OFF_AHI + off) =
                make_uint2(reinterpret_cast<uint32_t&>(h0), reinterpret_cast<uint32_t&>(h1));
            *reinterpret_cast<uint2*>(psm + OFF_ALO + off) =
                make_uint2(reinterpret_cast<uint32_t&>(l0), reinterpret_cast<uint32_t&>(l1));
        }
    };

    int t = blockIdx.x;
    // prologue: stage + convert tile t
    if (t < nTiles) {
        issueA(t);
        CP_WAIT0();
        convertA();           // each thread converts its own staged bytes
    }
    __syncthreads();

    while (t < nTiles) {
        int tn = t + GGRID;
        if (tn < nTiles) issueA(tn);     // async, register-free; hidden behind mma

        // ---- mma: D = Ah*Wh + Ah*Wl + Al*Wh ----
        float acc[2][8][4];
#pragma unroll
        for (int mt = 0; mt < 2; mt++)
#pragma unroll
            for (int nt = 0; nt < 8; nt++)
#pragma unroll
                for (int q = 0; q < 4; q++) acc[mt][nt][q] = 0.f;

#pragma unroll
        for (int kk = 0; kk < 8; kk++) {
            int k0 = kk * 16;
            uint32_t ah[2][4], al[2][4];
#pragma unroll
            for (int mt = 0; mt < 2; mt++) {
                uint32_t aoff = (uint32_t)((aRow + mt * 16) * LDA + k0 + aKh) * 2;
                ldx4(ah[mt], AHI + aoff);
                ldx4(al[mt], ALO + aoff);
            }
#pragma unroll
            for (int ntp = 0; ntp < 4; ntp++) {
                uint32_t boff = (uint32_t)((bRow + ntp * 16) * LDA + k0 + bKh) * 2;
                uint32_t bh[4], bl[4];
                ldx4(bh, WHI + boff);
                ldx4(bl, WLO + boff);
#pragma unroll
                for (int mt = 0; mt < 2; mt++) {
                    mma16816(acc[mt][2 * ntp + 0], ah[mt], bh[0], bh[1]);
                    mma16816(acc[mt][2 * ntp + 1], ah[mt], bh[2], bh[3]);
                    mma16816(acc[mt][2 * ntp + 0], ah[mt], bl[0], bl[1]);
                    mma16816(acc[mt][2 * ntp + 1], ah[mt], bl[2], bl[3]);
                    mma16816(acc[mt][2 * ntp + 0], al[mt], bh[0], bh[1]);
                    mma16816(acc[mt][2 * ntp + 1], al[mt], bh[2], bh[3]);
                }
            }
        }

        // ---- epilogue: bias + store + BN stats (smem accum) ----
        int row0 = t * 128;
#pragma unroll
        for (int mt = 0; mt < 2; mt++) {
            int r0 = row0 + warp_m * 32 + mt * 16 + (lane >> 2);
            int r1 = r0 + 8;
#pragma unroll
            for (int nt = 0; nt < 8; nt++) {
                int c = warp_n * 64 + nt * 8 + (lane & 3) * 2;
                float bx = s_bias[c], by = s_bias[c + 1];
                float v00 = acc[mt][nt][0] + bx, v01 = acc[mt][nt][1] + by;
                float v10 = acc[mt][nt][2] + bx, v11 = acc[mt][nt][3] + by;
                float cs0 = 0.f, cs1 = 0.f, cq0 = 0.f, cq1 = 0.f;
                if (r0 < Nn) {
                    *reinterpret_cast<float2*>(&g_Y[(size_t)r0 * DD + c]) = make_float2(v00, v01);
                    cs0 += v00; cs1 += v01;
                    cq0 = fmaf(v00, v00, cq0); cq1 = fmaf(v01, v01, cq1);
                }
                if (r1 < Nn) {
                    *reinterpret_cast<float2*>(&g_Y[(size_t)r1 * DD + c]) = make_float2(v10, v11);
                    cs0 += v10; cs1 += v11;
                    cq0 = fmaf(v10, v10, cq0); cq1 = fmaf(v11, v11, cq1);
                }
#pragma unroll
                for (int m = 4; m <= 16; m <<= 1) {
                    cs0 += __shfl_xor_sync(0xffffffffu, cs0, m);
                    cs1 += __shfl_xor_sync(0xffffffffu, cs1, m);
                    cq0 += __shfl_xor_sync(0xffffffffu, cq0, m);
                    cq1 += __shfl_xor_sync(0xffffffffu, cq1, m);
                }
                if ((lane >> 2) == 0) {
                    atomicAdd(&s_sum[c], cs0);     atomicAdd(&s_sum[c + 1], cs1);
                    atomicAdd(&s_sq[c], cq0);      atomicAdd(&s_sq[c + 1], cq1);
                }
            }
        }

        if (tn < nTiles) {
            CP_WAIT0();
            __syncthreads();   // all warps done reading AHI/ALO (mma) before overwrite
            convertA();
        }
        __syncthreads();
        t = tn;
    }

    // ---- flush BN stats once per CTA ----
    if (tid < DD) {
        float* osum = g_stat + (LAYER == 1 ? 0 : 2 * DD);
        atomicAdd(&osum[tid], s_sum[tid]);
        atomicAdd(&osum[DD + tid], s_sq[tid]);
    }
}

// ---------------------------------------------------------------------------
template <int LAYER>
__global__ void k_bn(const float* __restrict__ g, const float* __restrict__ beta, int N) {
    int j = threadIdx.x;
    const float* sum = g_stat + (LAYER == 1 ? 0 : 2 * DD);
    float invN = 1.0f / (float)N;
    float mean = sum[j] * invN;
    float var  = sum[DD + j] * invN - mean * mean;
    float sc = __ldg(&g[j]) * rsqrtf(var + 1e-5f);
    float* outS = g_stat + (LAYER == 1 ? 4 * DD : 6 * DD);
    outS[j] = sc;
    outS[DD + j] = __ldg(&beta[j]) - mean * sc;
}

// ---------------------------------------------------------------------------
__global__ void k_final(float* __restrict__ out, int n4) {
    const float4* Y4 = reinterpret_cast<const float4*>(g_Y);
    float4* o4 = reinterpret_cast<float4*>(out);
    for (int i = blockIdx.x * blockDim.x + threadIdx.x; i < n4; i += gridDim.x * blockDim.x) {
        int cb = (i & 31) * 4;
        float4 y = Y4[i];
        float4 r;
        r.x = fmaxf(fmaf(y.x, g_stat[6 * DD + cb + 0], g_stat[7 * DD + cb + 0]), 0.f);
        r.y = fmaxf(fmaf(y.y, g_stat[6 * DD + cb + 1], g_stat[7 * DD + cb + 1]), 0.f);
        r.z = fmaxf(fmaf(y.z, g_stat[6 * DD + cb + 2], g_stat[7 * DD + cb + 2]), 0.f);
        r.w = fmaxf(fmaf(y.w, g_stat[6 * DD + cb + 3], g_stat[7 * DD + cb + 3]), 0.f);
        o4[i] = r;
    }
}

// ---------------------------------------------------------------------------
extern "C" void kernel_launch(void* const* d_in, const int* in_sizes, int n_in,
                              void* d_out, int out_size) {
    const float* x   = (const float*)d_in[0];
    const int*   ei  = (const int*)d_in[1];
    const float* eps = (const float*)d_in[2];
    const float* W1  = (const float*)d_in[3];
    const float* b1  = (const float*)d_in[4];
    const float* g1  = (const float*)d_in[5];
    const float* be1 = (const float*)d_in[6];
    const float* W2  = (const float*)d_in[7];
    const float* b2  = (const float*)d_in[8];
    const float* g2  = (const float*)d_in[9];
    const float* be2 = (const float*)d_in[10];

    int N  = in_sizes[0] / DD;
    int E  = in_sizes[1] / 2;
    int n4 = N * (DD / 4);
    int gb = (N + 127) / 128;
    int nblk = (N + 511) / 512;
    int eb = (E + 255) / 256;

    cudaFuncSetAttribute((const void*)k_gemm_tc<1>, cudaFuncAttributeMaxDynamicSharedMemorySize, DYN_GEMM);
    cudaFuncSetAttribute((const void*)k_gemm_tc<2>, cudaFuncAttributeMaxDynamicSharedMemorySize, DYN_GEMM);

    int ggrid = gb < GGRID ? gb : GGRID;

    k_setup<<<400, 256>>>(ei, E, N, W1, W2);
    k_hist<<<eb, 256>>>(ei, E);
    k_scanA<<<nblk, 256>>>(N);
    k_scanC<<<nblk, 256>>>(N, nblk);
    k_fill<<<eb, 256>>>(ei, E);
    k_aggr<<<(N * 32 + 255) / 256, 256>>>((const float4*)x, eps, N, E);
    k_gemm_tc<1><<<ggrid, 256, DYN_GEMM>>>(b1, N, gb);
    k_bn<1><<<1, DD>>>(g1, be1, N);
    k_gemm_tc<2><<<ggrid, 256, DYN_GEMM>>>(b2, N, gb);
    k_bn<2><<<1, DD>>>(g2, be2, N);
    k_final<<<2048, 256>>>((float*)d_out, n4);
}

// round 11
// speedup vs baseline: 1.4819x; 1.0115x over previous
#include <cuda_runtime.h>
#include <cuda_bf16.h>
#include <cstdint>

#define DD 128
#define MAXN 100000
#define MAXE 655360
#define LDA 136                      // bf16 tile stride, conflict-free ldmatrix
#define RSTR 132                     // raw fp32 staging stride (floats), gemm2 only
#define GGRID 152                    // persistent GEMM grid (1 CTA/SM)

// gemm1 dyn smem: W hi/lo + double-buffered A hi/lo (no convert)
#define G1_WHI 0
#define G1_WLO 34816
#define G1_A0  69632                 // AHI0; ALO0 = +34816
#define G1_A1  139264                // AHI1; ALO1 = +34816
#define DYN_G1 208896
// gemm2 dyn smem: W hi/lo + A hi/lo + RAW fp32 staging (convert in-kernel)
#define G2_WHI 0
#define G2_WLO 34816
#define G2_AHI 69632
#define G2_ALO 104448
#define G2_RAW 139264
#define DYN_G2 (139264 + 128 * RSTR * 4)

// ---- scratch (no allocs allowed) -------------------------------------------
__device__ __align__(16) __nv_bfloat16 g_Ahi[(size_t)MAXN * DD];
__device__ __align__(16) __nv_bfloat16 g_Alo[(size_t)MAXN * DD];
__device__ __align__(16) float g_Y[(size_t)MAXN * DD];
__device__ __align__(16) __nv_bfloat16 g_Whi[2][DD * DD];
__device__ __align__(16) __nv_bfloat16 g_Wlo[2][DD * DD];
__device__ float g_part1[GGRID * 256];   // per-CTA [sum(128) | sq(128)]
__device__ float g_part2[GGRID * 256];
// CSR scratch
__device__ int g_cnt[MAXN + 1];
__device__ int g_off[MAXN + 1];
__device__ int g_cur[MAXN];
__device__ int g_srcid[MAXE];
__device__ int g_blksum[256];

#define SMEMU32(p) ((uint32_t)__cvta_generic_to_shared(p))

__device__ __forceinline__ void ldx4(uint32_t* r, uint32_t addr) {
    asm volatile("ldmatrix.sync.aligned.m8n8.x4.shared.b16 {%0,%1,%2,%3}, [%4];"
                 : "=r"(r[0]), "=r"(r[1]), "=r"(r[2]), "=r"(r[3]) : "r"(addr));
}
__device__ __forceinline__ void mma16816(float* c, const uint32_t* a, uint32_t b0, uint32_t b1) {
    asm volatile("mma.sync.aligned.m16n8k16.row.col.f32.bf16.bf16.f32 "
                 "{%0,%1,%2,%3}, {%4,%5,%6,%7}, {%8,%9}, {%0,%1,%2,%3};"
                 : "+f"(c[0]), "+f"(c[1]), "+f"(c[2]), "+f"(c[3])
                 : "r"(a[0]), "r"(a[1]), "r"(a[2]), "r"(a[3]), "r"(b0), "r"(b1));
}
__device__ __forceinline__ void cpasync16(uint32_t dst, const void* src, int sz) {
    asm volatile("cp.async.cg.shared.global [%0], [%1], 16, %2;"
                 :: "r"(dst), "l"(src), "r"(sz) : "memory");
}
#define CP_COMMIT() asm volatile("cp.async.commit_group;" ::: "memory")
#define CP_WAIT0()  asm volatile("cp.async.wait_group 0;" ::: "memory")

// per-block edge-dtype detect: int64 (values<2^31) => all odd words zero
__device__ __forceinline__ bool block_is_i64(const int* w, int base, int lim, int E) {
    __shared__ int s_or;
    if (threadIdx.x == 0) s_or = 0;
    __syncthreads();
    int e = base + threadIdx.x;
    int v = (e < lim) ? w[2 * (e % E) + 1] : 0;
    atomicOr(&s_or, v);
    __syncthreads();
    return s_or == 0;
}

// ---------------------------------------------------------------------------
__global__ void k_hist(const int* __restrict__ w, int E) {
    int e = blockIdx.x * blockDim.x + threadIdx.x;
    bool i64 = block_is_i64(w, blockIdx.x * blockDim.x, E, E);
    if (e >= E) return;
    int d = i64 ? __ldg(&w[2 * (E + e)]) : __ldg(&w[E + e]);
    atomicAdd(&g_cnt[d], 1);
}

// ---- scanA: per-512 block sums (+ W hi/lo split piggy-backed) --------------
__global__ void k_scanA(int Nn, const float* __restrict__ W1, const float* __restrict__ W2) {
    __shared__ int sm[256];
    int b = blockIdx.x, t = threadIdx.x;
    int gtid = b * 256 + t;
    if (gtid < 2 * DD * DD) {
        int layer = gtid >> 14, j = gtid & (DD * DD - 1);
        float v = (layer == 0) ? W1[j] : W2[j];
        __nv_bfloat16 h = __float2bfloat16_rn(v);
        g_Whi[layer][j] = h;
        g_Wlo[layer][j] = __float2bfloat16_rn(v - __bfloat162float(h));
    }
    int base = b * 512;
    int v = 0;
    if (base + t < Nn)       v += g_cnt[base + t];
    if (base + t + 256 < Nn) v += g_cnt[base + t + 256];
    sm[t] = v; __syncthreads();
    for (int o = 128; o > 0; o >>= 1) { if (t < o) sm[t] += sm[t + o]; __syncthreads(); }
    if (t == 0) g_blksum[b] = sm[0];
}
__global__ void k_scanC(int Nn, int nblk) {
    __shared__ int sm[256];
    __shared__ int s_off;
    int b = blockIdx.x, t = threadIdx.x;
    sm[t] = (t < b) ? g_blksum[t] : 0;
    __syncthreads();
    for (int o = 128; o > 0; o >>= 1) { if (t < o) sm[t] += sm[t + o]; __syncthreads(); }
    if (t == 0) s_off = sm[0];
    __syncthreads();
    int i0 = b * 512 + 2 * t, i1 = i0 + 1;
    int c0 = (i0 < Nn) ? g_cnt[i0] : 0;
    int c1 = (i1 < Nn) ? g_cnt[i1] : 0;
    int v = c0 + c1;
    sm[t] = v; __syncthreads();
    for (int o = 1; o < 256; o <<= 1) {
        int a = (t >= o) ? sm[t - o] : 0;
        __syncthreads(); sm[t] += a; __syncthreads();
    }
    int excl = sm[t] - v + s_off;
    if (i0 < Nn) { g_off[i0] = excl;      g_cur[i0] = excl; }
    if (i1 < Nn) { g_off[i1] = excl + c0; g_cur[i1] = excl + c0; }
}

// ---------------------------------------------------------------------------
__global__ void k_fill(const int* __restrict__ w, int E) {
    int e = blockIdx.x * blockDim.x + threadIdx.x;
    bool i64 = block_is_i64(w, blockIdx.x * blockDim.x, E, E);
    if (e >= E) return;
    int s, d;
    if (i64) { s = __ldg(&w[2 * e]); d = __ldg(&w[2 * (E + e)]); }
    else     { s = __ldg(&w[e]);     d = __ldg(&w[E + e]); }
    int p = atomicAdd(&g_cur[d], 1);
    g_srcid[p] = s;
}

// ---------------------------------------------------------------------------
// Warp per node: acc = (1+eps)x[n] + sum x[src]; write bf16 hi/lo planes.
// Also re-zeros g_cnt for next graph replay (safe: scanC already consumed it).
__global__ __launch_bounds__(256) void k_aggr(const float4* __restrict__ x,
                                              const float* __restrict__ eps, int Nn, int E) {
    for (int i = blockIdx.x * blockDim.x + threadIdx.x; i < Nn; i += gridDim.x * blockDim.x)
        g_cnt[i] = 0;
    int gw = (blockIdx.x * blockDim.x + threadIdx.x) >> 5;
    int lane = threadIdx.x & 31;
    if (gw >= Nn) return;
    float e = 1.0f + __ldg(eps);
    int beg = g_off[gw];
    int end = (gw + 1 < Nn) ? g_off[gw + 1] : E;
    float4 a = __ldg(&x[(size_t)gw * 32 + lane]);
    float4 acc = make_float4(a.x * e, a.y * e, a.z * e, a.w * e);
    int i = beg;
    for (; i + 3 < end; i += 4) {
        int s0 = __ldg(&g_srcid[i + 0]), s1 = __ldg(&g_srcid[i + 1]);
        int s2 = __ldg(&g_srcid[i + 2]), s3 = __ldg(&g_srcid[i + 3]);
        float4 v0 = __ldg(&x[(size_t)s0 * 32 + lane]);
        float4 v1 = __ldg(&x[(size_t)s1 * 32 + lane]);
        float4 v2 = __ldg(&x[(size_t)s2 * 32 + lane]);
        float4 v3 = __ldg(&x[(size_t)s3 * 32 + lane]);
        acc.x += v0.x + v1.x + v2.x + v3.x;
        acc.y += v0.y + v1.y + v2.y + v3.y;
        acc.z += v0.z + v1.z + v2.z + v3.z;
        acc.w += v0.w + v1.w + v2.w + v3.w;
    }
    for (; i < end; i++) {
        int s = __ldg(&g_srcid[i]);
        float4 v = __ldg(&x[(size_t)s * 32 + lane]);
        acc.x += v.x; acc.y += v.y; acc.z += v.z; acc.w += v.w;
    }
    __nv_bfloat162 h0 = __floats2bfloat162_rn(acc.x, acc.y);
    __nv_bfloat162 h1 = __floats2bfloat162_rn(acc.z, acc.w);
    __nv_bfloat162 l0 = __floats2bfloat162_rn(acc.x - __low2float(h0), acc.y - __high2float(h0));
    __nv_bfloat162 l1 = __floats2bfloat162_rn(acc.z - __low2float(h1), acc.w - __high2float(h1));
    size_t o = (size_t)gw * DD + lane * 4;
    *reinterpret_cast<uint2*>(&g_Ahi[o]) =
        make_uint2(reinterpret_cast<uint32_t&>(h0), reinterpret_cast<uint32_t&>(h1));
    *reinterpret_cast<uint2*>(&g_Alo[o]) =
        make_uint2(reinterpret_cast<uint32_t&>(l0), reinterpret_cast<uint32_t&>(l1));
}

// ---------------------------------------------------------------------------
// GEMM1: persistent; A pre-split in gmem -> cp.async straight into ldmatrix
// layout, double-buffered; no conversion phase at all.
__global__ __launch_bounds__(256) void k_gemm1(const float* __restrict__ bias,
                                               int Nn, int nTiles) {
    extern __shared__ char dynsm[];
    __shared__ float s_bias[DD];
    __shared__ float s_sum[DD], s_sq[DD];

    const uint32_t sbase = SMEMU32(dynsm);
    const uint32_t WHI = sbase + G1_WHI, WLO = sbase + G1_WLO;

    int tid = threadIdx.x, wid = tid >> 5, lane = tid & 31;
    if (tid < DD) {
        s_bias[tid] = __ldg(&bias[tid]);
        s_sum[tid] = 0.f; s_sq[tid] = 0.f;
    }
    int r = tid >> 1, c0 = (tid & 1) * 64;
    {
        const __nv_bfloat16* Wh = g_Whi[0] + r * DD;
        const __nv_bfloat16* Wl = g_Wlo[0] + r * DD;
        char* psm = dynsm;
#pragma unroll
        for (int i2 = 0; i2 < 16; i2++) {
            int c = c0 + i2 * 4;
            uint32_t off = (uint32_t)(r * LDA + c) * 2;
            *reinterpret_cast<uint2*>(psm + G1_WHI + off) = *reinterpret_cast<const uint2*>(Wh + c);
            *reinterpret_cast<uint2*>(psm + G1_WLO + off) = *reinterpret_cast<const uint2*>(Wl + c);
        }
    }
    __syncthreads();

    int warp_m = wid & 3, warp_n = wid >> 2;
    int aRow = warp_m * 32 + (lane & 15);
    int aKh  = (lane >> 4) * 8;
    int bRow = warp_n * 64 + (lane & 7) + ((lane >> 4) & 1) * 8;
    int bKh  = ((lane >> 3) & 1) * 8;

    auto issueA = [&](int tt, uint32_t bufOff) {
        int grow = tt * 128 + r;
        const __nv_bfloat16* sh_ = g_Ahi + (size_t)grow * DD + c0;
        const __nv_bfloat16* sl_ = g_Alo + (size_t)grow * DD + c0;
        int sz = (grow < Nn) ? 16 : 0;
        uint32_t d0 = sbase + bufOff + (uint32_t)(r * LDA + c0) * 2;
        uint32_t d1 = d0 + 34816;
#pragma unroll
        for (int i2 = 0; i2 < 8; i2++) {
            cpasync16(d0 + i2 * 16, sh_ + i2 * 8, sz);
            cpasync16(d1 + i2 * 16, sl_ + i2 * 8, sz);
        }
        CP_COMMIT();
    };

    int t = blockIdx.x;
    int buf = 0;
    if (t < nTiles) { issueA(t, G1_A0); CP_WAIT0(); }
    __syncthreads();

    while (t < nTiles) {
        int tn = t + gridDim.x;
        if (tn < nTiles) issueA(tn, buf ? G1_A0 : G1_A1);

        uint32_t AHIb = sbase + (buf ? G1_A1 : G1_A0);
        uint32_t ALOb = AHIb + 34816;
        float acc[2][8][4];
#pragma unroll
        for (int mt = 0; mt < 2; mt++)
#pragma unroll
            for (int nt = 0; nt < 8; nt++)
#pragma unroll
                for (int q = 0; q < 4; q++) acc[mt][nt][q] = 0.f;

#pragma unroll
        for (int kk = 0; kk < 8; kk++) {
            int k0 = kk * 16;
            uint32_t ah[2][4], al[2][4];
#pragma unroll
            for (int mt = 0; mt < 2; mt++) {
                uint32_t aoff = (uint32_t)((aRow + mt * 16) * LDA + k0 + aKh) * 2;
                ldx4(ah[mt], AHIb + aoff);
                ldx4(al[mt], ALOb + aoff);
            }
#pragma unroll
            for (int ntp = 0; ntp < 4; ntp++) {
                uint32_t boff = (uint32_t)((bRow + ntp * 16) * LDA + k0 + bKh) * 2;
                uint32_t bh[4], bl[4];
                ldx4(bh, WHI + boff);
                ldx4(bl, WLO + boff);
#pragma unroll
                for (int mt = 0; mt < 2; mt++) {
                    mma16816(acc[mt][2 * ntp + 0], ah[mt], bh[0], bh[1]);
                    mma16816(acc[mt][2 * ntp + 1], ah[mt], bh[2], bh[3]);
                    mma16816(acc[mt][2 * ntp + 0], ah[mt], bl[0], bl[1]);
                    mma16816(acc[mt][2 * ntp + 1], ah[mt], bl[2], bl[3]);
                    mma16816(acc[mt][2 * ntp + 0], al[mt], bh[0], bh[1]);
                    mma16816(acc[mt][2 * ntp + 1], al[mt], bh[2], bh[3]);
                }
            }
        }

        int row0 = t * 128;
#pragma unroll
        for (int mt = 0; mt < 2; mt++) {
            int r0 = row0 + warp_m * 32 + mt * 16 + (lane >> 2);
            int r1 = r0 + 8;
#pragma unroll
            for (int nt = 0; nt < 8; nt++) {
                int c = warp_n * 64 + nt * 8 + (lane & 3) * 2;
                float bx = s_bias[c], by = s_bias[c + 1];
                float v00 = acc[mt][nt][0] + bx, v01 = acc[mt][nt][1] + by;
                float v10 = acc[mt][nt][2] + bx, v11 = acc[mt][nt][3] + by;
                float cs0 = 0.f, cs1 = 0.f, cq0 = 0.f, cq1 = 0.f;
                if (r0 < Nn) {
                    *reinterpret_cast<float2*>(&g_Y[(size_t)r0 * DD + c]) = make_float2(v00, v01);
                    cs0 += v00; cs1 += v01;
                    cq0 = fmaf(v00, v00, cq0); cq1 = fmaf(v01, v01, cq1);
                }
                if (r1 < Nn) {
                    *reinterpret_cast<float2*>(&g_Y[(size_t)r1 * DD + c]) = make_float2(v10, v11);
                    cs0 += v10; cs1 += v11;
                    cq0 = fmaf(v10, v10, cq0); cq1 = fmaf(v11, v11, cq1);
                }
#pragma unroll
                for (int m = 4; m <= 16; m <<= 1) {
                    cs0 += __shfl_xor_sync(0xffffffffu, cs0, m);
                    cs1 += __shfl_xor_sync(0xffffffffu, cs1, m);
                    cq0 += __shfl_xor_sync(0xffffffffu, cq0, m);
                    cq1 += __shfl_xor_sync(0xffffffffu, cq1, m);
                }
                if ((lane >> 2) == 0) {
                    atomicAdd(&s_sum[c], cs0);     atomicAdd(&s_sum[c + 1], cs1);
                    atomicAdd(&s_sq[c], cq0);      atomicAdd(&s_sq[c + 1], cq1);
                }
            }
        }
        CP_WAIT0();
        __syncthreads();
        buf ^= 1;
        t = tn;
    }
    if (tid < DD) {
        g_part1[blockIdx.x * 256 + tid] = s_sum[tid];
        g_part1[blockIdx.x * 256 + 128 + tid] = s_sq[tid];
    }
}

// ---------------------------------------------------------------------------
// GEMM2: persistent; inline BN1 (reduce g_part1); RAW staging + convert.
__global__ __launch_bounds__(256) void k_gemm2(const float* __restrict__ bias,
                                               const float* __restrict__ gm, const float* __restrict__ bt,
                                               int Nn, int nTiles, int ngrid1) {
    extern __shared__ char dynsm[];
    __shared__ float s_bias[DD];
    __shared__ float s_s[DD], s_t[DD];
    __shared__ float s_sum[DD], s_sq[DD];

    const uint32_t sbase = SMEMU32(dynsm);
    const uint32_t WHI = sbase + G2_WHI, WLO = sbase + G2_WLO;
    const uint32_t AHI = sbase + G2_AHI, ALO = sbase + G2_ALO;
    const uint32_t RAWB = sbase + G2_RAW;

    int tid = threadIdx.x, wid = tid >> 5, lane = tid & 31;
    if (tid < DD) {
        s_bias[tid] = __ldg(&bias[tid]);
        s_sum[tid] = 0.f; s_sq[tid] = 0.f;
        float s = 0.f, q = 0.f;
        for (int c2 = 0; c2 < ngrid1; c2++) {
            s += g_part1[c2 * 256 + tid];
            q += g_part1[c2 * 256 + 128 + tid];
        }
        float invN = 1.0f / (float)Nn;
        float mean = s * invN;
        float var  = q * invN - mean * mean;
        float sc = __ldg(&gm[tid]) * rsqrtf(var + 1e-5f);
        s_s[tid] = sc;
        s_t[tid] = __ldg(&bt[tid]) - mean * sc;
    }
    int r = tid >> 1, c0 = (tid & 1) * 64;
    {
        const __nv_bfloat16* Wh = g_Whi[1] + r * DD;
        const __nv_bfloat16* Wl = g_Wlo[1] + r * DD;
        char* psm = dynsm;
#pragma unroll
        for (int i2 = 0; i2 < 16; i2++) {
            int c = c0 + i2 * 4;
            uint32_t off = (uint32_t)(r * LDA + c) * 2;
            *reinterpret_cast<uint2*>(psm + G2_WHI + off) = *reinterpret_cast<const uint2*>(Wh + c);
            *reinterpret_cast<uint2*>(psm + G2_WLO + off) = *reinterpret_cast<const uint2*>(Wl + c);
        }
    }
    __syncthreads();

    int warp_m = wid & 3, warp_n = wid >> 2;
    int aRow = warp_m * 32 + (lane & 15);
    int aKh  = (lane >> 4) * 8;
    int bRow = warp_n * 64 + (lane & 7) + ((lane >> 4) & 1) * 8;
    int bKh  = ((lane >> 3) & 1) * 8;

    auto issueA = [&](int tt) {
        int grow = tt * 128 + r;
        const float* src = g_Y + (size_t)grow * DD + c0;
        int sz = (grow < Nn) ? 16 : 0;
        uint32_t dst = RAWB + (uint32_t)(r * RSTR + c0) * 4;
#pragma unroll
        for (int i2 = 0; i2 < 16; i2++) cpasync16(dst + i2 * 16, src + i2 * 4, sz);
        CP_COMMIT();
    };
    auto convertA = [&]() {
        char* psm = dynsm;
#pragma unroll
        for (int i2 = 0; i2 < 16; i2++) {
            int c = c0 + i2 * 4;
            float4 v = *reinterpret_cast<float4*>(psm + G2_RAW + (uint32_t)(r * RSTR + c) * 4);
            v.x = fmaxf(fmaf(v.x, s_s[c + 0], s_t[c + 0]), 0.f);
            v.y = fmaxf(fmaf(v.y, s_s[c + 1], s_t[c + 1]), 0.f);
            v.z = fmaxf(fmaf(v.z, s_s[c + 2], s_t[c + 2]), 0.f);
            v.w = fmaxf(fmaf(v.w, s_s[c + 3], s_t[c + 3]), 0.f);
            __nv_bfloat162 h0 = __floats2bfloat162_rn(v.x, v.y);
            __nv_bfloat162 h1 = __floats2bfloat162_rn(v.z, v.w);
            __nv_bfloat162 l0 = __floats2bfloat162_rn(v.x - __low2float(h0), v.y - __high2float(h0));
            __nv_bfloat162 l1 = __floats2bfloat162_rn(v.z - __low2float(h1), v.w - __high2float(h1));
            uint32_t off = (uint32_t)(r * LDA + c) * 2;
            *reinterpret_cast<uint2*>(psm + G2_AHI + off) =
                make_uint2(reinterpret_cast<uint32_t&>(h0), reinterpret_cast<uint32_t&>(h1));
            *reinterpret_cast<uint2*>(psm + G2_ALO + off) =
                make_uint2(reinterpret_cast<uint32_t&>(l0), reinterpret_cast<uint32_t&>(l1));
        }
    };

    int t = blockIdx.x;
    if (t < nTiles) { issueA(t); CP_WAIT0(); convertA(); }
    __syncthreads();

    while (t < nTiles) {
        int tn = t + gridDim.x;
        if (tn < nTiles) issueA(tn);

        float acc[2][8][4];
#pragma unroll
        for (int mt = 0; mt < 2; mt++)
#pragma unroll
            for (int nt = 0; nt < 8; nt++)
#pragma unroll
                for (int q = 0; q < 4; q++) acc[mt][nt][q] = 0.f;

#pragma unroll
        for (int kk = 0; kk < 8; kk++) {
            int k0 = kk * 16;
            uint32_t ah[2][4], al[2][4];
#pragma unroll
            for (int mt = 0; mt < 2; mt++) {
                uint32_t aoff = (uint32_t)((aRow + mt * 16) * LDA + k0 + aKh) * 2;
                ldx4(ah[mt], AHI + aoff);
                ldx4(al[mt], ALO + aoff);
            }
#pragma unroll
            for (int ntp = 0; ntp < 4; ntp++) {
                uint32_t boff = (uint32_t)((bRow + ntp * 16) * LDA + k0 + bKh) * 2;
                uint32_t bh[4], bl[4];
                ldx4(bh, WHI + boff);
                ldx4(bl, WLO + boff);
#pragma unroll
                for (int mt = 0; mt < 2; mt++) {
                    mma16816(acc[mt][2 * ntp + 0], ah[mt], bh[0], bh[1]);
                    mma16816(acc[mt][2 * ntp + 1], ah[mt], bh[2], bh[3]);
                    mma16816(acc[mt][2 * ntp + 0], ah[mt], bl[0], bl[1]);
                    mma16816(acc[mt][2 * ntp + 1], ah[mt], bl[2], bl[3]);
                    mma16816(acc[mt][2 * ntp + 0], al[mt], bh[0], bh[1]);
                    mma16816(acc[mt][2 * ntp + 1], al[mt], bh[2], bh[3]);
                }
            }
        }

        int row0 = t * 128;
#pragma unroll
        for (int mt = 0; mt < 2; mt++) {
            int r0 = row0 + warp_m * 32 + mt * 16 + (lane >> 2);
            int r1 = r0 + 8;
#pragma unroll
            for (int nt = 0; nt < 8; nt++) {
                int c = warp_n * 64 + nt * 8 + (lane & 3) * 2;
                float bx = s_bias[c], by = s_bias[c + 1];
                float v00 = acc[mt][nt][0] + bx, v01 = acc[mt][nt][1] + by;
                float v10 = acc[mt][nt][2] + bx, v11 = acc[mt][nt][3] + by;
                float cs0 = 0.f, cs1 = 0.f, cq0 = 0.f, cq1 = 0.f;
                if (r0 < Nn) {
                    *reinterpret_cast<float2*>(&g_Y[(size_t)r0 * DD + c]) = make_float2(v00, v01);
                    cs0 += v00; cs1 += v01;
                    cq0 = fmaf(v00, v00, cq0); cq1 = fmaf(v01, v01, cq1);
                }
                if (r1 < Nn) {
                    *reinterpret_cast<float2*>(&g_Y[(size_t)r1 * DD + c]) = make_float2(v10, v11);
                    cs0 += v10; cs1 += v11;
                    cq0 = fmaf(v10, v10, cq0); cq1 = fmaf(v11, v11, cq1);
                }
#pragma unroll
                for (int m = 4; m <= 16; m <<= 1) {
                    cs0 += __shfl_xor_sync(0xffffffffu, cs0, m);
                    cs1 += __shfl_xor_sync(0xffffffffu, cs1, m);
                    cq0 += __shfl_xor_sync(0xffffffffu, cq0, m);
                    cq1 += __shfl_xor_sync(0xffffffffu, cq1, m);
                }
                if ((lane >> 2) == 0) {
                    atomicAdd(&s_sum[c], cs0);     atomicAdd(&s_sum[c + 1], cs1);
                    atomicAdd(&s_sq[c], cq0);      atomicAdd(&s_sq[c + 1], cq1);
                }
            }
        }

        if (tn < nTiles) {
            CP_WAIT0();
            __syncthreads();
            convertA();
        }
        __syncthreads();
        t = tn;
    }
    if (tid < DD) {
        g_part2[blockIdx.x * 256 + tid] = s_sum[tid];
        g_part2[blockIdx.x * 256 + 128 + tid] = s_sq[tid];
    }
}

// ---------------------------------------------------------------------------
// final: inline BN2 (reduce g_part2), then stream relu(Y*s+t) -> out.
__global__ __launch_bounds__(256) void k_final(float* __restrict__ out,
                                               const float* __restrict__ gm, const float* __restrict__ bt,
                                               int Nn, int n4, int ngrid2) {
    __shared__ float s_sc[DD], s_sh[DD];
    int tid = threadIdx.x;
    if (tid < DD) {
        float s = 0.f, q = 0.f;
        for (int c2 = 0; c2 < ngrid2; c2++) {
            s += g_part2[c2 * 256 + tid];
            q += g_part2[c2 * 256 + 128 + tid];
        }
        float invN = 1.0f / (float)Nn;
        float mean = s * invN;
        float var  = q * invN - mean * mean;
        float sc = __ldg(&gm[tid]) * rsqrtf(var + 1e-5f);
        s_sc[tid] = sc;
        s_sh[tid] = __ldg(&bt[tid]) - mean * sc;
    }
    __syncthreads();
    const float4* Y4 = reinterpret_cast<const float4*>(g_Y);
    float4* o4 = reinterpret_cast<float4*>(out);
    for (int i = blockIdx.x * blockDim.x + tid; i < n4; i += gridDim.x * blockDim.x) {
        int cb = (i & 31) * 4;
        float4 y = Y4[i];
        float4 r;
        r.x = fmaxf(fmaf(y.x, s_sc[cb + 0], s_sh[cb + 0]), 0.f);
        r.y = fmaxf(fmaf(y.y, s_sc[cb + 1], s_sh[cb + 1]), 0.f);
        r.z = fmaxf(fmaf(y.z, s_sc[cb + 2], s_sh[cb + 2]), 0.f);
        r.w = fmaxf(fmaf(y.w, s_sc[cb + 3], s_sh[cb + 3]), 0.f);
        o4[i] = r;
    }
}

// ---------------------------------------------------------------------------
extern "C" void kernel_launch(void* const* d_in, const int* in_sizes, int n_in,
                              void* d_out, int out_size) {
    const float* x   = (const float*)d_in[0];
    const int*   ei  = (const int*)d_in[1];
    const float* eps = (const float*)d_in[2];
    const float* W1  = (const float*)d_in[3];
    const float* b1  = (const float*)d_in[4];
    const float* g1  = (const float*)d_in[5];
    const float* be1 = (const float*)d_in[6];
    const float* W2  = (const float*)d_in[7];
    const float* b2  = (const float*)d_in[8];
    const float* g2  = (const float*)d_in[9];
    const float* be2 = (const float*)d_in[10];

    int N  = in_sizes[0] / DD;
    int E  = in_sizes[1] / 2;
    int n4 = N * (DD / 4);
    int gb = (N + 127) / 128;
    int nblk = (N + 511) / 512;
    int eb = (E + 255) / 256;

    cudaFuncSetAttribute((const void*)k_gemm1, cudaFuncAttributeMaxDynamicSharedMemorySize, DYN_G1);
    cudaFuncSetAttribute((const void*)k_gemm2, cudaFuncAttributeMaxDynamicSharedMemorySize, DYN_G2);

    int ggrid = gb < GGRID ? gb : GGRID;
    int swblk = nblk > 128 ? nblk : 128;   // scanA also hosts W split (needs >=128 blocks)

    k_hist<<<eb, 256>>>(ei, E);
    k_scanA<<<swblk, 256>>>(N, W1, W2);
    k_scanC<<<nblk, 256>>>(N, nblk);
    k_fill<<<eb, 256>>>(ei, E);
    k_aggr<<<(N * 32 + 255) / 256, 256>>>((const float4*)x, eps, N, E);
    k_gemm1<<<ggrid, 256, DYN_G1>>>(b1, N, gb);
    k_gemm2<<<ggrid, 256, DYN_G2>>>(b2, g1, be1, N, gb, ggrid);
    k_final<<<304, 256>>>((float*)d_out, g2, be2, N, n4, ggrid);
}

// round 12
// speedup vs baseline: 1.6728x; 1.1289x over previous
#include <cuda_runtime.h>
#include <cuda_bf16.h>
#include <cstdint>

#define DD 128
#define MAXN 100000
#define MAXE 655360
#define LDA 136
#define RSTR 132
#define GGRID 152

#define G1_WHI 0
#define G1_WLO 34816
#define G1_A0  69632
#define G1_A1  139264
#define DYN_G1 208896
#define G2_WHI 0
#define G2_WLO 34816
#define G2_AHI 69632
#define G2_ALO 104448
#define G2_RAW 139264
#define DYN_G2 (139264 + 128 * RSTR * 4)

// ---- scratch (no allocs allowed) -------------------------------------------
__device__ __align__(16) __nv_bfloat16 g_Ahi[(size_t)MAXN * DD];
__device__ __align__(16) __nv_bfloat16 g_Alo[(size_t)MAXN * DD];
__device__ __align__(16) float g_Y[(size_t)MAXN * DD];
__device__ __align__(16) __nv_bfloat16 g_Whi[2][DD * DD];
__device__ __align__(16) __nv_bfloat16 g_Wlo[2][DD * DD];
__device__ float g_part1[GGRID * 256];
__device__ float g_part2[GGRID * 256];
__device__ int g_cnt[MAXN + 1];
__device__ int g_off[MAXN + 1];
__device__ int g_cur[MAXN];
__device__ int g_srcid[MAXE];
__device__ int g_blksum[256];
__device__ int g_gbar[4];            // grid-barrier counters (zeroed by k_aggr)

#define SMEMU32(p) ((uint32_t)__cvta_generic_to_shared(p))

__device__ __forceinline__ void ldx4(uint32_t* r, uint32_t addr) {
    asm volatile("ldmatrix.sync.aligned.m8n8.x4.shared.b16 {%0,%1,%2,%3}, [%4];"
                 : "=r"(r[0]), "=r"(r[1]), "=r"(r[2]), "=r"(r[3]) : "r"(addr));
}
__device__ __forceinline__ void mma16816(float* c, const uint32_t* a, uint32_t b0, uint32_t b1) {
    asm volatile("mma.sync.aligned.m16n8k16.row.col.f32.bf16.bf16.f32 "
                 "{%0,%1,%2,%3}, {%4,%5,%6,%7}, {%8,%9}, {%0,%1,%2,%3};"
                 : "+f"(c[0]), "+f"(c[1]), "+f"(c[2]), "+f"(c[3])
                 : "r"(a[0]), "r"(a[1]), "r"(a[2]), "r"(a[3]), "r"(b0), "r"(b1));
}
__device__ __forceinline__ void cpasync16(uint32_t dst, const void* src, int sz) {
    asm volatile("cp.async.cg.shared.global [%0], [%1], 16, %2;"
                 :: "r"(dst), "l"(src), "r"(sz) : "memory");
}
#define CP_COMMIT() asm volatile("cp.async.commit_group;" ::: "memory")
#define CP_WAIT0()  asm volatile("cp.async.wait_group 0;" ::: "memory")

// device-wide barrier for persistent grids (all CTAs resident)
__device__ __forceinline__ void gridbar(int idx, int n) {
    __syncthreads();
    if (threadIdx.x == 0) {
        __threadfence();
        atomicAdd(&g_gbar[idx], 1);
        while (atomicAdd(&g_gbar[idx], 0) < n) { __nanosleep(60); }
    }
    __syncthreads();
}

// ---------------------------------------------------------------------------
// Persistent graph-prep: detect -> hist -> scanA(+W split) -> scanC -> fill
__global__ __launch_bounds__(256) void k_graph(const int* __restrict__ w, int E, int Nn,
                                               int nblk, int ngrid,
                                               const float* __restrict__ W1,
                                               const float* __restrict__ W2) {
    __shared__ int s_or;
    __shared__ int sm[256];
    __shared__ int s_off;
    int t = threadIdx.x, b = blockIdx.x;
    int gtid = b * 256 + t;
    int stride = ngrid * 256;

    // per-block i64 detect (sampled odd 32-bit words; int64 => all zero)
    if (t == 0) s_or = 0;
    __syncthreads();
    {
        int total = 2 * E;
        int step = total / 4096; if (step < 2) step = 2;
        int acc = 0;
        for (int i = t; i < 4096; i += 256) {
            long long idx = ((long long)i * step) | 1;
            if (idx < total) acc |= w[idx];
        }
        atomicOr(&s_or, acc);
    }
    __syncthreads();
    bool i64 = (s_or == 0);

    // hist
    for (int e = gtid; e < E; e += stride) {
        int d = i64 ? __ldg(&w[2 * (E + e)]) : __ldg(&w[E + e]);
        atomicAdd(&g_cnt[d], 1);
    }
    gridbar(0, ngrid);

    // W hi/lo split (one pass: 2*DD*DD = 32768 < grid threads)
    if (gtid < 2 * DD * DD) {
        int layer = gtid >> 14, j = gtid & (DD * DD - 1);
        float v = (layer == 0) ? W1[j] : W2[j];
        __nv_bfloat16 h = __float2bfloat16_rn(v);
        g_Whi[layer][j] = h;
        g_Wlo[layer][j] = __float2bfloat16_rn(v - __bfloat162float(h));
    }
    // scanA: per-512 block sums
    if (b < nblk) {
        int base = b * 512;
        int v = 0;
        if (base + t < Nn)       v += g_cnt[base + t];
        if (base + t + 256 < Nn) v += g_cnt[base + t + 256];
        sm[t] = v; __syncthreads();
        for (int o = 128; o > 0; o >>= 1) { if (t < o) sm[t] += sm[t + o]; __syncthreads(); }
        if (t == 0) g_blksum[b] = sm[0];
    }
    gridbar(1, ngrid);

    // scanC: offsets
    if (b < nblk) {
        sm[t] = (t < b) ? g_blksum[t] : 0;
        __syncthreads();
        for (int o = 128; o > 0; o >>= 1) { if (t < o) sm[t] += sm[t + o]; __syncthreads(); }
        if (t == 0) s_off = sm[0];
        __syncthreads();
        int i0 = b * 512 + 2 * t, i1 = i0 + 1;
        int c0 = (i0 < Nn) ? g_cnt[i0] : 0;
        int c1 = (i1 < Nn) ? g_cnt[i1] : 0;
        int v = c0 + c1;
        sm[t] = v; __syncthreads();
        for (int o = 1; o < 256; o <<= 1) {
            int a = (t >= o) ? sm[t - o] : 0;
            __syncthreads(); sm[t] += a; __syncthreads();
        }
        int excl = sm[t] - v + s_off;
        if (i0 < Nn) { g_off[i0] = excl;      g_cur[i0] = excl; }
        if (i1 < Nn) { g_off[i1] = excl + c0; g_cur[i1] = excl + c0; }
    }
    gridbar(2, ngrid);

    // fill
    for (int e = gtid; e < E; e += stride) {
        int s, d;
        if (i64) { s = __ldg(&w[2 * e]); d = __ldg(&w[2 * (E + e)]); }
        else     { s = __ldg(&w[e]);     d = __ldg(&w[E + e]); }
        int p = atomicAdd(&g_cur[d], 1);
        g_srcid[p] = s;
    }
}

// ---------------------------------------------------------------------------
// Warp per node: acc = (1+eps)x[n] + sum x[src]; write bf16 hi/lo planes.
// Re-zeros g_cnt and grid-barrier counters for the next replay.
__global__ __launch_bounds__(256) void k_aggr(const float4* __restrict__ x,
                                              const float* __restrict__ eps, int Nn, int E) {
    int gg = blockIdx.x * blockDim.x + threadIdx.x;
    if (gg < 4) g_gbar[gg] = 0;
    for (int i = gg; i < Nn; i += gridDim.x * blockDim.x) g_cnt[i] = 0;
    int gw = gg >> 5;
    int lane = threadIdx.x & 31;
    if (gw >= Nn) return;
    float e = 1.0f + __ldg(eps);
    int beg = g_off[gw];
    int end = (gw + 1 < Nn) ? g_off[gw + 1] : E;
    float4 a = __ldg(&x[(size_t)gw * 32 + lane]);
    float4 acc = make_float4(a.x * e, a.y * e, a.z * e, a.w * e);
    int i = beg;
    for (; i + 3 < end; i += 4) {
        int s0 = __ldg(&g_srcid[i + 0]), s1 = __ldg(&g_srcid[i + 1]);
        int s2 = __ldg(&g_srcid[i + 2]), s3 = __ldg(&g_srcid[i + 3]);
        float4 v0 = __ldg(&x[(size_t)s0 * 32 + lane]);
        float4 v1 = __ldg(&x[(size_t)s1 * 32 + lane]);
        float4 v2 = __ldg(&x[(size_t)s2 * 32 + lane]);
        float4 v3 = __ldg(&x[(size_t)s3 * 32 + lane]);
        acc.x += v0.x + v1.x + v2.x + v3.x;
        acc.y += v0.y + v1.y + v2.y + v3.y;
        acc.z += v0.z + v1.z + v2.z + v3.z;
        acc.w += v0.w + v1.w + v2.w + v3.w;
    }
    for (; i < end; i++) {
        int s = __ldg(&g_srcid[i]);
        float4 v = __ldg(&x[(size_t)s * 32 + lane]);
        acc.x += v.x; acc.y += v.y; acc.z += v.z; acc.w += v.w;
    }
    __nv_bfloat162 h0 = __floats2bfloat162_rn(acc.x, acc.y);
    __nv_bfloat162 h1 = __floats2bfloat162_rn(acc.z, acc.w);
    __nv_bfloat162 l0 = __floats2bfloat162_rn(acc.x - __low2float(h0), acc.y - __high2float(h0));
    __nv_bfloat162 l1 = __floats2bfloat162_rn(acc.z - __low2float(h1), acc.w - __high2float(h1));
    size_t o = (size_t)gw * DD + lane * 4;
    *reinterpret_cast<uint2*>(&g_Ahi[o]) =
        make_uint2(reinterpret_cast<uint32_t&>(h0), reinterpret_cast<uint32_t&>(h1));
    *reinterpret_cast<uint2*>(&g_Alo[o]) =
        make_uint2(reinterpret_cast<uint32_t&>(l0), reinterpret_cast<uint32_t&>(l1));
}

// ---------------------------------------------------------------------------
// GEMM1: persistent; cp.async pre-split A planes, double-buffered; BN stats in regs.
__global__ __launch_bounds__(256) void k_gemm1(const float* __restrict__ bias,
                                               int Nn, int nTiles) {
    extern __shared__ char dynsm[];
    __shared__ float s_bias[DD];
    __shared__ float s_sum[DD], s_sq[DD];

    const uint32_t sbase = SMEMU32(dynsm);
    const uint32_t WHI = sbase + G1_WHI, WLO = sbase + G1_WLO;

    int tid = threadIdx.x, wid = tid >> 5, lane = tid & 31;
    if (tid < DD) {
        s_bias[tid] = __ldg(&bias[tid]);
        s_sum[tid] = 0.f; s_sq[tid] = 0.f;
    }
    int r = tid >> 1, c0 = (tid & 1) * 64;
    {
        const __nv_bfloat16* Wh = g_Whi[0] + r * DD;
        const __nv_bfloat16* Wl = g_Wlo[0] + r * DD;
        char* psm = dynsm;
#pragma unroll
        for (int i2 = 0; i2 < 16; i2++) {
            int c = c0 + i2 * 4;
            uint32_t off = (uint32_t)(r * LDA + c) * 2;
            *reinterpret_cast<uint2*>(psm + G1_WHI + off) = *reinterpret_cast<const uint2*>(Wh + c);
            *reinterpret_cast<uint2*>(psm + G1_WLO + off) = *reinterpret_cast<const uint2*>(Wl + c);
        }
    }
    __syncthreads();

    int warp_m = wid & 3, warp_n = wid >> 2;
    int aRow = warp_m * 32 + (lane & 15);
    int aKh  = (lane >> 4) * 8;
    int bRow = warp_n * 64 + (lane & 7) + ((lane >> 4) & 1) * 8;
    int bKh  = ((lane >> 3) & 1) * 8;

    float psum[16], psq[16];
#pragma unroll
    for (int i = 0; i < 16; i++) { psum[i] = 0.f; psq[i] = 0.f; }

    auto issueA = [&](int tt, uint32_t bufOff) {
        int grow = tt * 128 + r;
        const __nv_bfloat16* sh_ = g_Ahi + (size_t)grow * DD + c0;
        const __nv_bfloat16* sl_ = g_Alo + (size_t)grow * DD + c0;
        int sz = (grow < Nn) ? 16 : 0;
        uint32_t d0 = sbase + bufOff + (uint32_t)(r * LDA + c0) * 2;
        uint32_t d1 = d0 + 34816;
#pragma unroll
        for (int i2 = 0; i2 < 8; i2++) {
            cpasync16(d0 + i2 * 16, sh_ + i2 * 8, sz);
            cpasync16(d1 + i2 * 16, sl_ + i2 * 8, sz);
        }
        CP_COMMIT();
    };

    int t = blockIdx.x;
    int buf = 0;
    if (t < nTiles) { issueA(t, G1_A0); CP_WAIT0(); }
    __syncthreads();

    while (t < nTiles) {
        int tn = t + gridDim.x;
        if (tn < nTiles) issueA(tn, buf ? G1_A0 : G1_A1);

        uint32_t AHIb = sbase + (buf ? G1_A1 : G1_A0);
        uint32_t ALOb = AHIb + 34816;
        float acc[2][8][4];
#pragma unroll
        for (int mt = 0; mt < 2; mt++)
#pragma unroll
            for (int nt = 0; nt < 8; nt++)
#pragma unroll
                for (int q = 0; q < 4; q++) acc[mt][nt][q] = 0.f;

#pragma unroll
        for (int kk = 0; kk < 8; kk++) {
            int k0 = kk * 16;
            uint32_t ah[2][4], al[2][4];
#pragma unroll
            for (int mt = 0; mt < 2; mt++) {
                uint32_t aoff = (uint32_t)((aRow + mt * 16) * LDA + k0 + aKh) * 2;
                ldx4(ah[mt], AHIb + aoff);
                ldx4(al[mt], ALOb + aoff);
            }
#pragma unroll
            for (int ntp = 0; ntp < 4; ntp++) {
                uint32_t boff = (uint32_t)((bRow + ntp * 16) * LDA + k0 + bKh) * 2;
                uint32_t bh[4], bl[4];
                ldx4(bh, WHI + boff);
                ldx4(bl, WLO + boff);
#pragma unroll
                for (int mt = 0; mt < 2; mt++) {
                    mma16816(acc[mt][2 * ntp + 0], ah[mt], bh[0], bh[1]);
                    mma16816(acc[mt][2 * ntp + 1], ah[mt], bh[2], bh[3]);
                    mma16816(acc[mt][2 * ntp + 0], ah[mt], bl[0], bl[1]);
                    mma16816(acc[mt][2 * ntp + 1], ah[mt], bl[2], bl[3]);
                    mma16816(acc[mt][2 * ntp + 0], al[mt], bh[0], bh[1]);
                    mma16816(acc[mt][2 * ntp + 1], al[mt], bh[2], bh[3]);
                }
            }
        }

        int row0 = t * 128;
#pragma unroll
        for (int mt = 0; mt < 2; mt++) {
            int r0 = row0 + warp_m * 32 + mt * 16 + (lane >> 2);
            int r1 = r0 + 8;
#pragma unroll
            for (int nt = 0; nt < 8; nt++) {
                int c = warp_n * 64 + nt * 8 + (lane & 3) * 2;
                float bx = s_bias[c], by = s_bias[c + 1];
                float v00 = acc[mt][nt][0] + bx, v01 = acc[mt][nt][1] + by;
                float v10 = acc[mt][nt][2] + bx, v11 = acc[mt][nt][3] + by;
                if (r0 < Nn) {
                    *reinterpret_cast<float2*>(&g_Y[(size_t)r0 * DD + c]) = make_float2(v00, v01);
                    psum[2 * nt] += v00; psum[2 * nt + 1] += v01;
                    psq[2 * nt] = fmaf(v00, v00, psq[2 * nt]);
                    psq[2 * nt + 1] = fmaf(v01, v01, psq[2 * nt + 1]);
                }
                if (r1 < Nn) {
                    *reinterpret_cast<float2*>(&g_Y[(size_t)r1 * DD + c]) = make_float2(v10, v11);
                    psum[2 * nt] += v10; psum[2 * nt + 1] += v11;
                    psq[2 * nt] = fmaf(v10, v10, psq[2 * nt]);
                    psq[2 * nt + 1] = fmaf(v11, v11, psq[2 * nt + 1]);
                }
            }
        }
        CP_WAIT0();
        __syncthreads();
        buf ^= 1;
        t = tn;
    }

    // final stat reduction (once per kernel)
#pragma unroll
    for (int nt = 0; nt < 8; nt++) {
        float s0 = psum[2 * nt], s1 = psum[2 * nt + 1];
        float q0 = psq[2 * nt],  q1 = psq[2 * nt + 1];
#pragma unroll
        for (int m = 4; m <= 16; m <<= 1) {
            s0 += __shfl_xor_sync(0xffffffffu, s0, m);
            s1 += __shfl_xor_sync(0xffffffffu, s1, m);
            q0 += __shfl_xor_sync(0xffffffffu, q0, m);
            q1 += __shfl_xor_sync(0xffffffffu, q1, m);
        }
        if ((lane >> 2) == 0) {
            int c = warp_n * 64 + nt * 8 + (lane & 3) * 2;
            atomicAdd(&s_sum[c], s0);     atomicAdd(&s_sum[c + 1], s1);
            atomicAdd(&s_sq[c], q0);      atomicAdd(&s_sq[c + 1], q1);
        }
    }
    __syncthreads();
    if (tid < DD) {
        g_part1[blockIdx.x * 256 + tid] = s_sum[tid];
        g_part1[blockIdx.x * 256 + 128 + tid] = s_sq[tid];
    }
}

// ---------------------------------------------------------------------------
// GEMM2: persistent; inline BN1; RAW staging + convert; BN stats in regs.
__global__ __launch_bounds__(256) void k_gemm2(const float* __restrict__ bias,
                                               const float* __restrict__ gm, const float* __restrict__ bt,
                                               int Nn, int nTiles, int ngrid1) {
    extern __shared__ char dynsm[];
    __shared__ float s_bias[DD];
    __shared__ float s_s[DD], s_t[DD];
    __shared__ float s_sum[DD], s_sq[DD];

    const uint32_t sbase = SMEMU32(dynsm);
    const uint32_t WHI = sbase + G2_WHI, WLO = sbase + G2_WLO;
    const uint32_t AHI = sbase + G2_AHI, ALO = sbase + G2_ALO;
    const uint32_t RAWB = sbase + G2_RAW;

    int tid = threadIdx.x, wid = tid >> 5, lane = tid & 31;
    if (tid < DD) {
        s_bias[tid] = __ldg(&bias[tid]);
        s_sum[tid] = 0.f; s_sq[tid] = 0.f;
        float s = 0.f, q = 0.f;
        for (int c2 = 0; c2 < ngrid1; c2++) {
            s += g_part1[c2 * 256 + tid];
            q += g_part1[c2 * 256 + 128 + tid];
        }
        float invN = 1.0f / (float)Nn;
        float mean = s * invN;
        float var  = q * invN - mean * mean;
        float sc = __ldg(&gm[tid]) * rsqrtf(var + 1e-5f);
        s_s[tid] = sc;
        s_t[tid] = __ldg(&bt[tid]) - mean * sc;
    }
    int r = tid >> 1, c0 = (tid & 1) * 64;
    {
        const __nv_bfloat16* Wh = g_Whi[1] + r * DD;
        const __nv_bfloat16* Wl = g_Wlo[1] + r * DD;
        char* psm = dynsm;
#pragma unroll
        for (int i2 = 0; i2 < 16; i2++) {
            int c = c0 + i2 * 4;
            uint32_t off = (uint32_t)(r * LDA + c) * 2;
            *reinterpret_cast<uint2*>(psm + G2_WHI + off) = *reinterpret_cast<const uint2*>(Wh + c);
            *reinterpret_cast<uint2*>(psm + G2_WLO + off) = *reinterpret_cast<const uint2*>(Wl + c);
        }
    }
    __syncthreads();

    int warp_m = wid & 3, warp_n = wid >> 2;
    int aRow = warp_m * 32 + (lane & 15);
    int aKh  = (lane >> 4) * 8;
    int bRow = warp_n * 64 + (lane & 7) + ((lane >> 4) & 1) * 8;
    int bKh  = ((lane >> 3) & 1) * 8;

    float psum[16], psq[16];
#pragma unroll
    for (int i = 0; i < 16; i++) { psum[i] = 0.f; psq[i] = 0.f; }

    auto issueA = [&](int tt) {
        int grow = tt * 128 + r;
        const float* src = g_Y + (size_t)grow * DD + c0;
        int sz = (grow < Nn) ? 16 : 0;
        uint32_t dst = RAWB + (uint32_t)(r * RSTR + c0) * 4;
#pragma unroll
        for (int i2 = 0; i2 < 16; i2++) cpasync16(dst + i2 * 16, src + i2 * 4, sz);
        CP_COMMIT();
    };
    auto convertA = [&]() {
        char* psm = dynsm;
#pragma unroll
        for (int i2 = 0; i2 < 16; i2++) {
            int c = c0 + i2 * 4;
            float4 v = *reinterpret_cast<float4*>(psm + G2_RAW + (uint32_t)(r * RSTR + c) * 4);
            v.x = fmaxf(fmaf(v.x, s_s[c + 0], s_t[c + 0]), 0.f);
            v.y = fmaxf(fmaf(v.y, s_s[c + 1], s_t[c + 1]), 0.f);
            v.z = fmaxf(fmaf(v.z, s_s[c + 2], s_t[c + 2]), 0.f);
            v.w = fmaxf(fmaf(v.w, s_s[c + 3], s_t[c + 3]), 0.f);
            __nv_bfloat162 h0 = __floats2bfloat162_rn(v.x, v.y);
            __nv_bfloat162 h1 = __floats2bfloat162_rn(v.z, v.w);
            __nv_bfloat162 l0 = __floats2bfloat162_rn(v.x - __low2float(h0), v.y - __high2float(h0));
            __nv_bfloat162 l1 = __floats2bfloat162_rn(v.z - __low2float(h1), v.w - __high2float(h1));
            uint32_t off = (uint32_t)(r * LDA + c) * 2;
            *reinterpret_cast<uint2*>(psm + G2_AHI + off) =
                make_uint2(reinterpret_cast<uint32_t&>(h0), reinterpret_cast<uint32_t&>(h1));
            *reinterpret_cast<uint2*>(psm + G2_ALO + off) =
                make_uint2(reinterpret_cast<uint32_t&>(l0), reinterpret_cast<uint32_t&>(l1));
        }
    };

    int t = blockIdx.x;
    if (t < nTiles) { issueA(t); CP_WAIT0(); convertA(); }
    __syncthreads();

    while (t < nTiles) {
        int tn = t + gridDim.x;
        if (tn < nTiles) issueA(tn);

        float acc[2][8][4];
#pragma unroll
        for (int mt = 0; mt < 2; mt++)
#pragma unroll
            for (int nt = 0; nt < 8; nt++)
#pragma unroll
                for (int q = 0; q < 4; q++) acc[mt][nt][q] = 0.f;

#pragma unroll
        for (int kk = 0; kk < 8; kk++) {
            int k0 = kk * 16;
            uint32_t ah[2][4], al[2][4];
#pragma unroll
            for (int mt = 0; mt < 2; mt++) {
                uint32_t aoff = (uint32_t)((aRow + mt * 16) * LDA + k0 + aKh) * 2;
                ldx4(ah[mt], AHI + aoff);
                ldx4(al[mt], ALO + aoff);
            }
#pragma unroll
            for (int ntp = 0; ntp < 4; ntp++) {
                uint32_t boff = (uint32_t)((bRow + ntp * 16) * LDA + k0 + bKh) * 2;
                uint32_t bh[4], bl[4];
                ldx4(bh, WHI + boff);
                ldx4(bl, WLO + boff);
#pragma unroll
                for (int mt = 0; mt < 2; mt++) {
                    mma16816(acc[mt][2 * ntp + 0], ah[mt], bh[0], bh[1]);
                    mma16816(acc[mt][2 * ntp + 1], ah[mt], bh[2], bh[3]);
                    mma16816(acc[mt][2 * ntp + 0], ah[mt], bl[0], bl[1]);
                    mma16816(acc[mt][2 * ntp + 1], ah[mt], bl[2], bl[3]);
                    mma16816(acc[mt][2 * ntp + 0], al[mt], bh[0], bh[1]);
                    mma16816(acc[mt][2 * ntp + 1], al[mt], bh[2], bh[3]);
                }
            }
        }

        int row0 = t * 128;
#pragma unroll
        for (int mt = 0; mt < 2; mt++) {
            int r0 = row0 + warp_m * 32 + mt * 16 + (lane >> 2);
            int r1 = r0 + 8;
#pragma unroll
            for (int nt = 0; nt < 8; nt++) {
                int c = warp_n * 64 + nt * 8 + (lane & 3) * 2;
                float bx = s_bias[c], by = s_bias[c + 1];
                float v00 = acc[mt][nt][0] + bx, v01 = acc[mt][nt][1] + by;
                float v10 = acc[mt][nt][2] + bx, v11 = acc[mt][nt][3] + by;
                if (r0 < Nn) {
                    *reinterpret_cast<float2*>(&g_Y[(size_t)r0 * DD + c]) = make_float2(v00, v01);
                    psum[2 * nt] += v00; psum[2 * nt + 1] += v01;
                    psq[2 * nt] = fmaf(v00, v00, psq[2 * nt]);
                    psq[2 * nt + 1] = fmaf(v01, v01, psq[2 * nt + 1]);
                }
                if (r1 < Nn) {
                    *reinterpret_cast<float2*>(&g_Y[(size_t)r1 * DD + c]) = make_float2(v10, v11);
                    psum[2 * nt] += v10; psum[2 * nt + 1] += v11;
                    psq[2 * nt] = fmaf(v10, v10, psq[2 * nt]);
                    psq[2 * nt + 1] = fmaf(v11, v11, psq[2 * nt + 1]);
                }
            }
        }

        if (tn < nTiles) {
            CP_WAIT0();
            __syncthreads();
            convertA();
        }
        __syncthreads();
        t = tn;
    }

#pragma unroll
    for (int nt = 0; nt < 8; nt++) {
        float s0 = psum[2 * nt], s1 = psum[2 * nt + 1];
        float q0 = psq[2 * nt],  q1 = psq[2 * nt + 1];
#pragma unroll
        for (int m = 4; m <= 16; m <<= 1) {
            s0 += __shfl_xor_sync(0xffffffffu, s0, m);
            s1 += __shfl_xor_sync(0xffffffffu, s1, m);
            q0 += __shfl_xor_sync(0xffffffffu, q0, m);
            q1 += __shfl_xor_sync(0xffffffffu, q1, m);
        }
        if ((lane >> 2) == 0) {
            int c = warp_n * 64 + nt * 8 + (lane & 3) * 2;
            atomicAdd(&s_sum[c], s0);     atomicAdd(&s_sum[c + 1], s1);
            atomicAdd(&s_sq[c], q0);      atomicAdd(&s_sq[c + 1], q1);
        }
    }
    __syncthreads();
    if (tid < DD) {
        g_part2[blockIdx.x * 256 + tid] = s_sum[tid];
        g_part2[blockIdx.x * 256 + 128 + tid] = s_sq[tid];
    }
}

// ---------------------------------------------------------------------------
__global__ __launch_bounds__(256) void k_final(float* __restrict__ out,
                                               const float* __restrict__ gm, const float* __restrict__ bt,
                                               int Nn, int n4, int ngrid2) {
    __shared__ float s_sc[DD], s_sh[DD];
    int tid = threadIdx.x;
    if (tid < DD) {
        float s = 0.f, q = 0.f;
        for (int c2 = 0; c2 < ngrid2; c2++) {
            s += g_part2[c2 * 256 + tid];
            q += g_part2[c2 * 256 + 128 + tid];
        }
        float invN = 1.0f / (float)Nn;
        float mean = s * invN;
        float var  = q * invN - mean * mean;
        float sc = __ldg(&gm[tid]) * rsqrtf(var + 1e-5f);
        s_sc[tid] = sc;
        s_sh[tid] = __ldg(&bt[tid]) - mean * sc;
    }
    __syncthreads();
    const float4* Y4 = reinterpret_cast<const float4*>(g_Y);
    float4* o4 = reinterpret_cast<float4*>(out);
    for (int i = blockIdx.x * blockDim.x + tid; i < n4; i += gridDim.x * blockDim.x) {
        int cb = (i & 31) * 4;
        float4 y = Y4[i];
        float4 r;
        r.x = fmaxf(fmaf(y.x, s_sc[cb + 0], s_sh[cb + 0]), 0.f);
        r.y = fmaxf(fmaf(y.y, s_sc[cb + 1], s_sh[cb + 1]), 0.f);
        r.z = fmaxf(fmaf(y.z, s_sc[cb + 2], s_sh[cb + 2]), 0.f);
        r.w = fmaxf(fmaf(y.w, s_sc[cb + 3], s_sh[cb + 3]), 0.f);
        o4[i] = r;
    }
}

// ---------------------------------------------------------------------------
extern "C" void kernel_launch(void* const* d_in, const int* in_sizes, int n_in,
                              void* d_out, int out_size) {
    const float* x   = (const float*)d_in[0];
    const int*   ei  = (const int*)d_in[1];
    const float* eps = (const float*)d_in[2];
    const float* W1  = (const float*)d_in[3];
    const float* b1  = (const float*)d_in[4];
    const float* g1  = (const float*)d_in[5];
    const float* be1 = (const float*)d_in[6];
    const float* W2  = (const float*)d_in[7];
    const float* b2  = (const float*)d_in[8];
    const float* g2  = (const float*)d_in[9];
    const float* be2 = (const float*)d_in[10];

    int N  = in_sizes[0] / DD;
    int E  = in_sizes[1] / 2;
    int n4 = N * (DD / 4);
    int gb = (N + 127) / 128;
    int nblk = (N + 511) / 512;

    cudaFuncSetAttribute((const void*)k_gemm1, cudaFuncAttributeMaxDynamicSharedMemorySize, DYN_G1);
    cudaFuncSetAttribute((const void*)k_gemm2, cudaFuncAttributeMaxDynamicSharedMemorySize, DYN_G2);

    int ggrid = gb < GGRID ? gb : GGRID;
    int pgrid = 304;                       // persistent graph-prep grid (all resident)

    k_graph<<<pgrid, 256>>>(ei, E, N, nblk, pgrid, W1, W2);
    k_aggr<<<(N * 32 + 255) / 256, 256>>>((const float4*)x, eps, N, E);
    k_gemm1<<<ggrid, 256, DYN_G1>>>(b1, N, gb);
    k_gemm2<<<ggrid, 256, DYN_G2>>>(b2, g1, be1, N, gb, ggrid);
    k_final<<<304, 256>>>((float*)d_out, g2, be2, N, n4, ggrid);
}